// round 1
// baseline (speedup 1.0000x reference)
#include <cuda_runtime.h>
#include <math.h>

// Problem constants (fixed shapes per reference)
#define NNA 40000
#define NNB 40000
#define EED 400000
#define DD  256
#define HH  8
#define CCH 32

// ---------------- scratch (static device globals; no allocation) ----------------
__device__ float g_hA[NNA * DD];
__device__ float g_hB[NNB * DD];
__device__ float g_relBA[NNA * DD];   // relation 1 (B->A) aggregated messages (unnormalized)
__device__ float g_relAA[NNA * DD];   // relation 2 (A->A)
__device__ float g_relAB[NNB * DD];   // relation 0 (A->B)
__device__ float g_al0[NNA * HH];     // (h_A . attn_l[0])
__device__ float g_ar0[NNB * HH];     // (h_B . attn_r[0])
__device__ float g_al1[NNB * HH];     // (h_B . attn_l[1])
__device__ float g_ar1[NNA * HH];     // (h_A . attn_r[1])
__device__ float g_al2[NNA * HH];     // (h_A . attn_l[2])
__device__ float g_ar2[NNA * HH];     // (h_A . attn_r[2])
__device__ float g_mBA[NNA * HH];     // segment max buffers
__device__ float g_mAA[NNA * HH];
__device__ float g_mAB[NNB * HH];
__device__ float g_dBA[NNA * HH];     // segment exp-sum buffers
__device__ float g_dAA[NNA * HH];
__device__ float g_dAB[NNB * HH];

// ---------------- helpers ----------------
__device__ __forceinline__ float warp_sum(float v) {
#pragma unroll
    for (int o = 16; o; o >>= 1) v += __shfl_xor_sync(0xffffffffu, v, o);
    return v;
}

__device__ __forceinline__ float leaky02(float x) {
    return x > 0.f ? x : 0.2f * x;
}

// atomic float max via signed/unsigned int ordering trick.
// Works for all finite floats when buffer is initialized to a very negative
// float (we use byte-fill 0xFE -> -1.69e38).
__device__ __forceinline__ void atomicMaxFloat(float* addr, float v) {
    if (v >= 0.f) atomicMax((int*)addr, __float_as_int(v));
    else          atomicMin((unsigned int*)addr, __float_as_uint(v));
}

__device__ __forceinline__ void red_add_v4(float* p, float4 v) {
    asm volatile("red.global.add.v4.f32 [%0], {%1,%2,%3,%4};"
                 :: "l"(p), "f"(v.x), "f"(v.y), "f"(v.z), "f"(v.w)
                 : "memory");
}

// ---------------- SGEMM: C[M,256] = A[M,256] @ W[256,256] + bias ----------------
// BM=128, BN=128, BK=16, 256 threads, 8x8 microtile
__global__ __launch_bounds__(256, 2)
void sgemm_bias_kernel(const float* __restrict__ A, const float* __restrict__ W,
                       const float* __restrict__ bias, float* __restrict__ Cout, int M) {
    __shared__ float As[16][128];
    __shared__ float Bs[16][128];

    const int row0 = blockIdx.x * 128;
    const int col0 = blockIdx.y * 128;
    const int tid  = threadIdx.x;
    const int tx   = tid & 15;   // 0..15 -> n
    const int ty   = tid >> 4;   // 0..15 -> m

    float acc[8][8];
#pragma unroll
    for (int i = 0; i < 8; i++)
#pragma unroll
        for (int j = 0; j < 8; j++) acc[i][j] = 0.f;

    for (int k0 = 0; k0 < 256; k0 += 16) {
        // load A tile 128x16 (512 float4, 2 per thread), store transposed
#pragma unroll
        for (int p = 0; p < 2; p++) {
            int f  = tid + 256 * p;     // 0..511
            int r  = f >> 2;            // row in tile 0..127
            int c4 = f & 3;             // float4 idx in row
            int gr = row0 + r;
            float4 v = make_float4(0.f, 0.f, 0.f, 0.f);
            if (gr < M) v = *(const float4*)(A + (size_t)gr * 256 + k0 + c4 * 4);
            As[c4 * 4 + 0][r] = v.x;
            As[c4 * 4 + 1][r] = v.y;
            As[c4 * 4 + 2][r] = v.z;
            As[c4 * 4 + 3][r] = v.w;
        }
        // load B tile 16x128
#pragma unroll
        for (int p = 0; p < 2; p++) {
            int f  = tid + 256 * p;
            int r  = f >> 5;            // 0..15
            int c4 = f & 31;            // 0..31
            float4 v = *(const float4*)(W + (size_t)(k0 + r) * 256 + col0 + c4 * 4);
            *(float4*)&Bs[r][c4 * 4] = v;
        }
        __syncthreads();
#pragma unroll
        for (int kk = 0; kk < 16; kk++) {
            float a[8], b[8];
#pragma unroll
            for (int i = 0; i < 8; i++) a[i] = As[kk][ty * 8 + i];
#pragma unroll
            for (int j = 0; j < 8; j++) b[j] = Bs[kk][tx * 8 + j];
#pragma unroll
            for (int i = 0; i < 8; i++)
#pragma unroll
                for (int j = 0; j < 8; j++) acc[i][j] = fmaf(a[i], b[j], acc[i][j]);
        }
        __syncthreads();
    }

#pragma unroll
    for (int i = 0; i < 8; i++) {
        int gr = row0 + ty * 8 + i;
        if (gr < M) {
#pragma unroll
            for (int j = 0; j < 8; j += 4) {
                int gc = col0 + tx * 8 + j;
                float4 v;
                v.x = acc[i][j + 0] + bias[gc + 0];
                v.y = acc[i][j + 1] + bias[gc + 1];
                v.z = acc[i][j + 2] + bias[gc + 2];
                v.w = acc[i][j + 3] + bias[gc + 3];
                *(float4*)(Cout + (size_t)gr * 256 + gc) = v;
            }
        }
    }
}

// ---------------- per-node alpha dots: o[n,h] = sum_c h[n,h,c]*a[h,c] ----------------
// up to 4 (attn, out) pairs per call; block = 1 node (8 warps = heads, lanes = c)
__global__ __launch_bounds__(256)
void alphas_kernel(const float* __restrict__ h, int N,
                   const float* __restrict__ a0, float* __restrict__ o0,
                   const float* __restrict__ a1, float* __restrict__ o1,
                   const float* __restrict__ a2, float* __restrict__ o2,
                   const float* __restrict__ a3, float* __restrict__ o3) {
    int n = blockIdx.x;
    if (n >= N) return;
    int hh   = threadIdx.x >> 5;
    int lane = threadIdx.x & 31;
    float x = h[(size_t)n * 256 + hh * 32 + lane];
    if (a0) { float s = warp_sum(x * a0[hh * 32 + lane]); if (lane == 0) o0[n * 8 + hh] = s; }
    if (a1) { float s = warp_sum(x * a1[hh * 32 + lane]); if (lane == 0) o1[n * 8 + hh] = s; }
    if (a2) { float s = warp_sum(x * a2[hh * 32 + lane]); if (lane == 0) o2[n * 8 + hh] = s; }
    if (a3) { float s = warp_sum(x * a3[hh * 32 + lane]); if (lane == 0) o3[n * 8 + hh] = s; }
}

// ---------------- edge pass 1: segment max ----------------
// thread t handles (edge, head); m must be pre-filled with very negative floats
__global__ __launch_bounds__(256)
void edge_max_kernel(const int* __restrict__ edge, int E,
                     const float* __restrict__ al, const float* __restrict__ ar,
                     float* __restrict__ m) {
    int t = blockIdx.x * blockDim.x + threadIdx.x;
    if (t >= E * 8) return;
    int e = t >> 3, hh = t & 7;
    int src = edge[e];
    int dst = edge[E + e];
    float v = leaky02(al[src * 8 + hh] + ar[dst * 8 + hh]);
    atomicMaxFloat(&m[dst * 8 + hh], v);
}

// ---------------- edge pass 2: exp, denom-add, message scatter ----------------
// warp per edge; lanes 0..7 compute per-head exp + denom atomicAdd, then the
// whole warp scatters h_src * ex into rel via vector reductions (2 x 32 float4)
__global__ __launch_bounds__(256)
void edge_msg_kernel(const int* __restrict__ edge, int E,
                     const float* __restrict__ al, const float* __restrict__ ar,
                     const float* __restrict__ m, float* __restrict__ den,
                     const float* __restrict__ hsrc, float* __restrict__ rel) {
    int w    = (blockIdx.x * blockDim.x + threadIdx.x) >> 5;
    int lane = threadIdx.x & 31;
    if (w >= E) return;
    int src = edge[w];
    int dst = edge[E + w];

    float ex = 0.f;
    if (lane < 8) {
        float v = leaky02(al[src * 8 + lane] + ar[dst * 8 + lane]);
        ex = __expf(v - m[dst * 8 + lane]);
        atomicAdd(&den[dst * 8 + lane], ex);
    }

    const float4* hs = (const float4*)(hsrc + (size_t)src * 256);
    float*        rp = rel + (size_t)dst * 256;
#pragma unroll
    for (int it = 0; it < 2; it++) {
        int f = lane + 32 * it;                            // float4 idx 0..63; head = f>>3
        float exh = __shfl_sync(0xffffffffu, ex, f >> 3);
        float4 v = hs[f];
        v.x *= exh; v.y *= exh; v.z *= exh; v.w *= exh;
        red_add_v4(rp + f * 4, v);
    }
}

// ---------------- beta combine for A (R=3: relBA, relAA, h) ----------------
__global__ __launch_bounds__(256)
void beta_A_kernel(const float* __restrict__ h,
                   const float* __restrict__ rel0, const float* __restrict__ den0,
                   const float* __restrict__ rel1, const float* __restrict__ den1,
                   const float* __restrict__ rel_l, const float* __restrict__ rel_r,
                   float* __restrict__ out, int N) {
    int n = blockIdx.x;
    if (n >= N) return;
    int hh   = threadIdx.x >> 5;
    int lane = threadIdx.x & 31;
    size_t idx = (size_t)n * 256 + hh * 32 + lane;

    float x  = h[idx];
    float d0 = den0[n * 8 + hh];
    float d1 = den1[n * 8 + hh];
    float i0 = d0 > 0.f ? 1.f / d0 : 0.f;
    float i1 = d1 > 0.f ? 1.f / d1 : 0.f;
    float e0 = rel0[idx] * i0;
    float e1 = rel1[idx] * i1;
    float e2 = x;

    float rl = rel_l[hh * 32 + lane];
    float rr = rel_r[hh * 32 + lane];
    float bl = warp_sum(x * rl);
    float b0 = warp_sum(e0 * rr);
    float b1 = warp_sum(e1 * rr);
    float b2 = warp_sum(e2 * rr);

    float s0 = leaky02(bl + b0);
    float s1 = leaky02(bl + b1);
    float s2 = leaky02(bl + b2);
    float mx = fmaxf(s0, fmaxf(s1, s2));
    float w0 = __expf(s0 - mx), w1 = __expf(s1 - mx), w2 = __expf(s2 - mx);
    float inv = 1.f / (w0 + w1 + w2);
    float o = (e0 * w0 + e1 * w1 + e2 * w2) * inv;
    out[idx] = fmaxf(o, 0.f);
}

// ---------------- beta combine for B (R=2: relAB, h) ----------------
__global__ __launch_bounds__(256)
void beta_B_kernel(const float* __restrict__ h,
                   const float* __restrict__ rel0, const float* __restrict__ den0,
                   const float* __restrict__ rel_l, const float* __restrict__ rel_r,
                   float* __restrict__ out, int N) {
    int n = blockIdx.x;
    if (n >= N) return;
    int hh   = threadIdx.x >> 5;
    int lane = threadIdx.x & 31;
    size_t idx = (size_t)n * 256 + hh * 32 + lane;

    float x  = h[idx];
    float d0 = den0[n * 8 + hh];
    float i0 = d0 > 0.f ? 1.f / d0 : 0.f;
    float e0 = rel0[idx] * i0;
    float e1 = x;

    float rl = rel_l[hh * 32 + lane];
    float rr = rel_r[hh * 32 + lane];
    float bl = warp_sum(x * rl);
    float b0 = warp_sum(e0 * rr);
    float b1 = warp_sum(e1 * rr);

    float s0 = leaky02(bl + b0);
    float s1 = leaky02(bl + b1);
    float mx = fmaxf(s0, s1);
    float w0 = __expf(s0 - mx), w1 = __expf(s1 - mx);
    float inv = 1.f / (w0 + w1);
    float o = (e0 * w0 + e1 * w1) * inv;
    out[idx] = fmaxf(o, 0.f);
}

// ---------------- launch ----------------
extern "C" void kernel_launch(void* const* d_in, const int* in_sizes, int n_in,
                              void* d_out, int out_size) {
    const float* x_A     = (const float*)d_in[0];
    const float* x_B     = (const float*)d_in[1];
    const int*   e_ab    = (const int*)d_in[2];
    const int*   e_ba    = (const int*)d_in[3];
    const int*   e_aa    = (const int*)d_in[4];
    const float* W_A     = (const float*)d_in[5];
    const float* b_A     = (const float*)d_in[6];
    const float* W_B     = (const float*)d_in[7];
    const float* b_B     = (const float*)d_in[8];
    const float* attn_l  = (const float*)d_in[9];   // [3,8,32]
    const float* attn_r  = (const float*)d_in[10];  // [3,8,32]
    const float* rel_l_A = (const float*)d_in[11];
    const float* rel_r_A = (const float*)d_in[12];
    const float* rel_l_B = (const float*)d_in[13];
    const float* rel_r_B = (const float*)d_in[14];
    float* out = (float*)d_out;

    // device pointers to scratch (cudaGetSymbolAddress is not a stream op; capture-safe)
    void *p_relBA, *p_relAA, *p_relAB;
    void *p_mBA, *p_mAA, *p_mAB, *p_dBA, *p_dAA, *p_dAB;
    void *p_hA, *p_hB;
    void *p_al0, *p_ar0, *p_al1, *p_ar1, *p_al2, *p_ar2;
    cudaGetSymbolAddress(&p_relBA, g_relBA);
    cudaGetSymbolAddress(&p_relAA, g_relAA);
    cudaGetSymbolAddress(&p_relAB, g_relAB);
    cudaGetSymbolAddress(&p_mBA, g_mBA);
    cudaGetSymbolAddress(&p_mAA, g_mAA);
    cudaGetSymbolAddress(&p_mAB, g_mAB);
    cudaGetSymbolAddress(&p_dBA, g_dBA);
    cudaGetSymbolAddress(&p_dAA, g_dAA);
    cudaGetSymbolAddress(&p_dAB, g_dAB);
    cudaGetSymbolAddress(&p_hA, g_hA);
    cudaGetSymbolAddress(&p_hB, g_hB);
    cudaGetSymbolAddress(&p_al0, g_al0);
    cudaGetSymbolAddress(&p_ar0, g_ar0);
    cudaGetSymbolAddress(&p_al1, g_al1);
    cudaGetSymbolAddress(&p_ar1, g_ar1);
    cudaGetSymbolAddress(&p_al2, g_al2);
    cudaGetSymbolAddress(&p_ar2, g_ar2);

    // init: zero accumulators; fill maxes with 0xFE bytes -> -1.69e38 (acts as -inf)
    cudaMemsetAsync(p_relBA, 0, sizeof(float) * NNA * DD, 0);
    cudaMemsetAsync(p_relAA, 0, sizeof(float) * NNA * DD, 0);
    cudaMemsetAsync(p_relAB, 0, sizeof(float) * NNB * DD, 0);
    cudaMemsetAsync(p_dBA, 0, sizeof(float) * NNA * HH, 0);
    cudaMemsetAsync(p_dAA, 0, sizeof(float) * NNA * HH, 0);
    cudaMemsetAsync(p_dAB, 0, sizeof(float) * NNB * HH, 0);
    cudaMemsetAsync(p_mBA, 0xFE, sizeof(float) * NNA * HH, 0);
    cudaMemsetAsync(p_mAA, 0xFE, sizeof(float) * NNA * HH, 0);
    cudaMemsetAsync(p_mAB, 0xFE, sizeof(float) * NNB * HH, 0);

    float* hA = (float*)p_hA;
    float* hB = (float*)p_hB;
    float* al0 = (float*)p_al0; float* ar0 = (float*)p_ar0;
    float* al1 = (float*)p_al1; float* ar1 = (float*)p_ar1;
    float* al2 = (float*)p_al2; float* ar2 = (float*)p_ar2;

    // 1) projections
    {
        dim3 grid((NNA + 127) / 128, 2);
        sgemm_bias_kernel<<<grid, 256>>>(x_A, W_A, b_A, hA, NNA);
        sgemm_bias_kernel<<<grid, 256>>>(x_B, W_B, b_B, hB, NNB);
    }

    // 2) node alphas
    alphas_kernel<<<NNA, 256>>>(hA, NNA,
                                attn_l + 0 * 256, al0,
                                attn_r + 1 * 256, ar1,
                                attn_l + 2 * 256, al2,
                                attn_r + 2 * 256, ar2);
    alphas_kernel<<<NNB, 256>>>(hB, NNB,
                                attn_r + 0 * 256, ar0,
                                attn_l + 1 * 256, al1,
                                (const float*)nullptr, (float*)nullptr,
                                (const float*)nullptr, (float*)nullptr);

    // 3) edge passes
    int gmax = (EED * 8 + 255) / 256;
    int gmsg = (EED * 8 + 255) / 256;  // warp per edge, 8 warps/block -> E*32 threads
    // pass 1: segment max
    edge_max_kernel<<<gmax, 256>>>(e_ba, EED, al1, ar1, (float*)p_mBA);
    edge_max_kernel<<<gmax, 256>>>(e_aa, EED, al2, ar2, (float*)p_mAA);
    edge_max_kernel<<<gmax, 256>>>(e_ab, EED, al0, ar0, (float*)p_mAB);
    // pass 2: exp + denom + message scatter  (E warps -> E*32 threads)
    int gm2 = (EED * 32 + 255) / 256;
    edge_msg_kernel<<<gm2, 256>>>(e_ba, EED, al1, ar1, (float*)p_mBA, (float*)p_dBA, hB, (float*)p_relBA);
    edge_msg_kernel<<<gm2, 256>>>(e_aa, EED, al2, ar2, (float*)p_mAA, (float*)p_dAA, hA, (float*)p_relAA);
    edge_msg_kernel<<<gm2, 256>>>(e_ab, EED, al0, ar0, (float*)p_mAB, (float*)p_dAB, hA, (float*)p_relAB);

    // 4) beta combine + relu -> output
    beta_A_kernel<<<NNA, 256>>>(hA, (float*)p_relBA, (float*)p_dBA,
                                (float*)p_relAA, (float*)p_dAA,
                                rel_l_A, rel_r_A, out, NNA);
    beta_B_kernel<<<NNB, 256>>>(hB, (float*)p_relAB, (float*)p_dAB,
                                rel_l_B, rel_r_B, out + (size_t)NNA * 256, NNB);

    (void)in_sizes; (void)n_in; (void)out_size;
}

// round 2
// speedup vs baseline: 1.3248x; 1.3248x over previous
#include <cuda_runtime.h>
#include <cuda_bf16.h>
#include <math.h>
#include <stdint.h>

// Problem constants (fixed shapes per reference)
#define NNA 40000
#define NNB 40000
#define EED 400000
#define DD  256
#define HH  8

// ---------------- scratch (static device globals; no allocation) ----------------
__device__ float g_hA[NNA * DD];
__device__ float g_hB[NNB * DD];
__device__ float g_relBA[NNA * DD];
__device__ float g_relAA[NNA * DD];
__device__ float g_relAB[NNB * DD];
__device__ float g_al0[NNA * HH];
__device__ float g_ar0[NNB * HH];
__device__ float g_al1[NNB * HH];
__device__ float g_ar1[NNA * HH];
__device__ float g_al2[NNA * HH];
__device__ float g_ar2[NNA * HH];
__device__ float g_dBA[NNA * HH];
__device__ float g_dAA[NNA * HH];
__device__ float g_dAB[NNB * HH];

// ---------------- helpers ----------------
__device__ __forceinline__ float warp_sum(float v) {
#pragma unroll
    for (int o = 16; o; o >>= 1) v += __shfl_xor_sync(0xffffffffu, v, o);
    return v;
}
__device__ __forceinline__ float leaky02(float x) { return x > 0.f ? x : 0.2f * x; }

__device__ __forceinline__ void red_add_v4(float* p, float4 v) {
    asm volatile("red.global.add.v4.f32 [%0], {%1,%2,%3,%4};"
                 :: "l"(p), "f"(v.x), "f"(v.y), "f"(v.z), "f"(v.w) : "memory");
}

__device__ __forceinline__ uint32_t smem_u32(const void* p) {
    uint32_t a;
    asm("{ .reg .u64 t; cvta.to.shared.u64 t, %1; cvt.u32.u64 %0, t; }" : "=r"(a) : "l"(p));
    return a;
}

__device__ __forceinline__ void ldsm4(uint32_t* r, uint32_t a) {
    asm volatile("ldmatrix.sync.aligned.m8n8.x4.shared.b16 {%0,%1,%2,%3}, [%4];"
                 : "=r"(r[0]), "=r"(r[1]), "=r"(r[2]), "=r"(r[3]) : "r"(a));
}
__device__ __forceinline__ void ldsm4t(uint32_t* r, uint32_t a) {
    asm volatile("ldmatrix.sync.aligned.m8n8.x4.trans.shared.b16 {%0,%1,%2,%3}, [%4];"
                 : "=r"(r[0]), "=r"(r[1]), "=r"(r[2]), "=r"(r[3]) : "r"(a));
}
__device__ __forceinline__ void mma16816(float* d, const uint32_t* a, uint32_t b0, uint32_t b1) {
    asm volatile("mma.sync.aligned.m16n8k16.row.col.f32.bf16.bf16.f32 "
                 "{%0,%1,%2,%3}, {%4,%5,%6,%7}, {%8,%9}, {%0,%1,%2,%3};"
                 : "+f"(d[0]), "+f"(d[1]), "+f"(d[2]), "+f"(d[3])
                 : "r"(a[0]), "r"(a[1]), "r"(a[2]), "r"(a[3]), "r"(b0), "r"(b1));
}

// split fp32 pair into bf16 hi pair + bf16 lo pair (packed b32 each)
__device__ __forceinline__ void split_pair(float a, float b, uint32_t& hi, uint32_t& lo) {
    __nv_bfloat16 ah = __float2bfloat16(a);
    __nv_bfloat16 bh = __float2bfloat16(b);
    __nv_bfloat16 al = __float2bfloat16(a - __bfloat162float(ah));
    __nv_bfloat16 bl = __float2bfloat16(b - __bfloat162float(bh));
    __nv_bfloat162 H; H.x = ah; H.y = bh;
    __nv_bfloat162 L; L.x = al; L.y = bl;
    hi = *reinterpret_cast<uint32_t*>(&H);
    lo = *reinterpret_cast<uint32_t*>(&L);
}

// ---------------- GEMM: C[M,256] = A[M,256] @ W[256,256] + bias  (bf16x3 split) ----
// CTA tile 128x64, BK=32, 256 threads, warps 2(m) x 4(n), warp tile 64x16
#define ASTR 40   // bf16 elems per A smem row (32 + 8 pad) -> conflict-free ldsm
#define BSTR 72   // bf16 elems per B smem row (64 + 8 pad) -> conflict-free ldsm.trans
__global__ __launch_bounds__(256)
void gemm_bf16x3(const float* __restrict__ A, const float* __restrict__ W,
                 const float* __restrict__ bias, float* __restrict__ C, int M) {
    __shared__ __nv_bfloat16 sAhi[128 * ASTR];
    __shared__ __nv_bfloat16 sAlo[128 * ASTR];
    __shared__ __nv_bfloat16 sBhi[32 * BSTR];
    __shared__ __nv_bfloat16 sBlo[32 * BSTR];

    const int tid  = threadIdx.x;
    const int lane = tid & 31;
    const int wid  = tid >> 5;
    const int wm   = wid & 1;    // 0..1 : 64 rows each
    const int wn   = wid >> 1;   // 0..3 : 16 cols each
    const int row0 = blockIdx.x * 128;
    const int col0 = blockIdx.y * 64;

    float acc[4][2][4];
#pragma unroll
    for (int i = 0; i < 4; i++)
#pragma unroll
        for (int j = 0; j < 2; j++)
#pragma unroll
            for (int k = 0; k < 4; k++) acc[i][j][k] = 0.f;

    float4 av[4], bv[2];

    // prologue load k0 = 0
#pragma unroll
    for (int p = 0; p < 4; p++) {
        int f = tid + 256 * p, r = f >> 3, c = (f & 7) * 4;
        int gr = row0 + r;
        av[p] = (gr < M) ? __ldg((const float4*)(A + (size_t)gr * 256 + c))
                         : make_float4(0.f, 0.f, 0.f, 0.f);
    }
#pragma unroll
    for (int p = 0; p < 2; p++) {
        int f = tid + 256 * p, r = f >> 4, c = (f & 15) * 4;
        bv[p] = __ldg((const float4*)(W + (size_t)r * 256 + col0 + c));
    }

    for (int kb = 0; kb < 8; kb++) {
        // store current tile to smem (convert+split)
#pragma unroll
        for (int p = 0; p < 4; p++) {
            int f = tid + 256 * p, r = f >> 3, c = (f & 7) * 4;
            uint32_t h01, l01, h23, l23;
            split_pair(av[p].x, av[p].y, h01, l01);
            split_pair(av[p].z, av[p].w, h23, l23);
            *(uint2*)&sAhi[r * ASTR + c] = make_uint2(h01, h23);
            *(uint2*)&sAlo[r * ASTR + c] = make_uint2(l01, l23);
        }
#pragma unroll
        for (int p = 0; p < 2; p++) {
            int f = tid + 256 * p, r = f >> 4, c = (f & 15) * 4;
            uint32_t h01, l01, h23, l23;
            split_pair(bv[p].x, bv[p].y, h01, l01);
            split_pair(bv[p].z, bv[p].w, h23, l23);
            *(uint2*)&sBhi[r * BSTR + c] = make_uint2(h01, h23);
            *(uint2*)&sBlo[r * BSTR + c] = make_uint2(l01, l23);
        }
        __syncthreads();

        // prefetch next tile into regs (overlaps mma below)
        if (kb < 7) {
            int k0 = (kb + 1) * 32;
#pragma unroll
            for (int p = 0; p < 4; p++) {
                int f = tid + 256 * p, r = f >> 3, c = (f & 7) * 4;
                int gr = row0 + r;
                av[p] = (gr < M) ? __ldg((const float4*)(A + (size_t)gr * 256 + k0 + c))
                                 : make_float4(0.f, 0.f, 0.f, 0.f);
            }
#pragma unroll
            for (int p = 0; p < 2; p++) {
                int f = tid + 256 * p, r = f >> 4, c = (f & 15) * 4;
                bv[p] = __ldg((const float4*)(W + (size_t)(k0 + r) * 256 + col0 + c));
            }
        }

        // compute on smem tile
#pragma unroll
        for (int kk = 0; kk < 32; kk += 16) {
            uint32_t ahi[4][4], alo[4][4], bh[4], bl[4];
            int arow = wm * 64 + (lane & 15);
            int acol = kk + ((lane >> 4) << 3);
#pragma unroll
            for (int mt = 0; mt < 4; mt++)
                ldsm4(ahi[mt], smem_u32(&sAhi[(arow + mt * 16) * ASTR + acol]));
            {
                int brow = kk + (lane & 7) + ((lane >> 3) & 1) * 8;
                int bcol = wn * 16 + ((lane >> 4) << 3);
                ldsm4t(bh, smem_u32(&sBhi[brow * BSTR + bcol]));
                ldsm4t(bl, smem_u32(&sBlo[brow * BSTR + bcol]));
            }
#pragma unroll
            for (int mt = 0; mt < 4; mt++)
                ldsm4(alo[mt], smem_u32(&sAlo[(arow + mt * 16) * ASTR + acol]));

#pragma unroll
            for (int mt = 0; mt < 4; mt++)
#pragma unroll
                for (int nt = 0; nt < 2; nt++) {
                    mma16816(acc[mt][nt], ahi[mt], bh[nt * 2], bh[nt * 2 + 1]);
                    mma16816(acc[mt][nt], ahi[mt], bl[nt * 2], bl[nt * 2 + 1]);
                    mma16816(acc[mt][nt], alo[mt], bh[nt * 2], bh[nt * 2 + 1]);
                }
        }
        __syncthreads();
    }

    // epilogue: bias + store
    float bb[2][2];
#pragma unroll
    for (int nt = 0; nt < 2; nt++) {
        int gc = col0 + wn * 16 + nt * 8 + (lane & 3) * 2;
        bb[nt][0] = __ldg(bias + gc);
        bb[nt][1] = __ldg(bias + gc + 1);
    }
#pragma unroll
    for (int mt = 0; mt < 4; mt++) {
#pragma unroll
        for (int half = 0; half < 2; half++) {
            int gr = row0 + wm * 64 + mt * 16 + (lane >> 2) + half * 8;
            if (gr < M) {
#pragma unroll
                for (int nt = 0; nt < 2; nt++) {
                    int gc = col0 + wn * 16 + nt * 8 + (lane & 3) * 2;
                    float2 o;
                    o.x = acc[mt][nt][half * 2 + 0] + bb[nt][0];
                    o.y = acc[mt][nt][half * 2 + 1] + bb[nt][1];
                    *(float2*)(C + (size_t)gr * 256 + gc) = o;
                }
            }
        }
    }
}

// ---------------- alphas: o[n,h] = sum_c h[n,h,c]*a[h,c], up to 4 vectors ------
template <int NV>
__global__ __launch_bounds__(256)
void alphas2_kernel(const float* __restrict__ h, int N,
                    const float* __restrict__ v0, const float* __restrict__ v1,
                    const float* __restrict__ v2, const float* __restrict__ v3,
                    float* __restrict__ o0, float* __restrict__ o1,
                    float* __restrict__ o2, float* __restrict__ o3) {
    __shared__ float sa[NV][256];
    const float* vs[4] = {v0, v1, v2, v3};
#pragma unroll
    for (int v = 0; v < NV; v++) sa[v][threadIdx.x] = __ldg(vs[v] + threadIdx.x);
    __syncthreads();

    int t = blockIdx.x * 256 + threadIdx.x;
    int n = t >> 3, hh = t & 7;
    if (n >= N) return;
    const float4* hp = (const float4*)(h + (size_t)n * 256 + hh * 32);
    float s[NV];
#pragma unroll
    for (int v = 0; v < NV; v++) s[v] = 0.f;
#pragma unroll
    for (int c4 = 0; c4 < 8; c4++) {
        float4 hv = __ldg(hp + c4);
#pragma unroll
        for (int v = 0; v < NV; v++) {
            float4 a = *(const float4*)&sa[v][hh * 32 + c4 * 4];
            s[v] += hv.x * a.x + hv.y * a.y + hv.z * a.z + hv.w * a.w;
        }
    }
    float* os[4] = {o0, o1, o2, o3};
#pragma unroll
    for (int v = 0; v < NV; v++) os[v][n * 8 + hh] = s[v];
}

// ---------------- single edge pass: exp (no max shift), denom, message scatter --
__global__ __launch_bounds__(256)
void edge_msg_kernel(const int* __restrict__ edge, int E,
                     const float* __restrict__ al, const float* __restrict__ ar,
                     float* __restrict__ den,
                     const float* __restrict__ hsrc, float* __restrict__ rel) {
    int w    = (blockIdx.x * blockDim.x + threadIdx.x) >> 5;
    int lane = threadIdx.x & 31;
    if (w >= E) return;
    int src = __ldg(edge + w);
    int dst = __ldg(edge + E + w);

    float ex = 0.f;
    if (lane < 8) {
        float v = leaky02(__ldg(al + src * 8 + lane) + __ldg(ar + dst * 8 + lane));
        ex = __expf(v);   // softmax is shift-invariant; no max pass needed
        atomicAdd(&den[dst * 8 + lane], ex);
    }

    const float4* hs = (const float4*)(hsrc + (size_t)src * 256);
    float*        rp = rel + (size_t)dst * 256;
#pragma unroll
    for (int it = 0; it < 2; it++) {
        int f = lane + 32 * it;   // float4 idx 0..63; head = f>>3
        float exh = __shfl_sync(0xffffffffu, ex, f >> 3);
        float4 v = __ldg(hs + f);
        v.x *= exh; v.y *= exh; v.z *= exh; v.w *= exh;
        red_add_v4(rp + f * 4, v);
    }
}

// ---------------- beta combine for A (R=3: relBA, relAA, h) ----------------
__global__ __launch_bounds__(256)
void beta_A_kernel(const float* __restrict__ h,
                   const float* __restrict__ rel0, const float* __restrict__ den0,
                   const float* __restrict__ rel1, const float* __restrict__ den1,
                   const float* __restrict__ rel_l, const float* __restrict__ rel_r,
                   float* __restrict__ out, int N) {
    int n = blockIdx.x;
    if (n >= N) return;
    int hh   = threadIdx.x >> 5;
    int lane = threadIdx.x & 31;
    size_t idx = (size_t)n * 256 + hh * 32 + lane;

    float x  = h[idx];
    float d0 = den0[n * 8 + hh];
    float d1 = den1[n * 8 + hh];
    float i0 = d0 > 0.f ? 1.f / d0 : 0.f;
    float i1 = d1 > 0.f ? 1.f / d1 : 0.f;
    float e0 = rel0[idx] * i0;
    float e1 = rel1[idx] * i1;
    float e2 = x;

    float rl = rel_l[hh * 32 + lane];
    float rr = rel_r[hh * 32 + lane];
    float bl = warp_sum(x * rl);
    float b0 = warp_sum(e0 * rr);
    float b1 = warp_sum(e1 * rr);
    float b2 = warp_sum(e2 * rr);

    float s0 = leaky02(bl + b0);
    float s1 = leaky02(bl + b1);
    float s2 = leaky02(bl + b2);
    float mx = fmaxf(s0, fmaxf(s1, s2));
    float w0 = __expf(s0 - mx), w1 = __expf(s1 - mx), w2 = __expf(s2 - mx);
    float inv = 1.f / (w0 + w1 + w2);
    float o = (e0 * w0 + e1 * w1 + e2 * w2) * inv;
    out[idx] = fmaxf(o, 0.f);
}

// ---------------- beta combine for B (R=2: relAB, h) ----------------
__global__ __launch_bounds__(256)
void beta_B_kernel(const float* __restrict__ h,
                   const float* __restrict__ rel0, const float* __restrict__ den0,
                   const float* __restrict__ rel_l, const float* __restrict__ rel_r,
                   float* __restrict__ out, int N) {
    int n = blockIdx.x;
    if (n >= N) return;
    int hh   = threadIdx.x >> 5;
    int lane = threadIdx.x & 31;
    size_t idx = (size_t)n * 256 + hh * 32 + lane;

    float x  = h[idx];
    float d0 = den0[n * 8 + hh];
    float i0 = d0 > 0.f ? 1.f / d0 : 0.f;
    float e0 = rel0[idx] * i0;
    float e1 = x;

    float rl = rel_l[hh * 32 + lane];
    float rr = rel_r[hh * 32 + lane];
    float bl = warp_sum(x * rl);
    float b0 = warp_sum(e0 * rr);
    float b1 = warp_sum(e1 * rr);

    float s0 = leaky02(bl + b0);
    float s1 = leaky02(bl + b1);
    float mx = fmaxf(s0, s1);
    float w0 = __expf(s0 - mx), w1 = __expf(s1 - mx);
    float inv = 1.f / (w0 + w1);
    float o = (e0 * w0 + e1 * w1) * inv;
    out[idx] = fmaxf(o, 0.f);
}

// ---------------- launch ----------------
extern "C" void kernel_launch(void* const* d_in, const int* in_sizes, int n_in,
                              void* d_out, int out_size) {
    const float* x_A     = (const float*)d_in[0];
    const float* x_B     = (const float*)d_in[1];
    const int*   e_ab    = (const int*)d_in[2];
    const int*   e_ba    = (const int*)d_in[3];
    const int*   e_aa    = (const int*)d_in[4];
    const float* W_A     = (const float*)d_in[5];
    const float* b_A     = (const float*)d_in[6];
    const float* W_B     = (const float*)d_in[7];
    const float* b_B     = (const float*)d_in[8];
    const float* attn_l  = (const float*)d_in[9];   // [3,8,32]
    const float* attn_r  = (const float*)d_in[10];  // [3,8,32]
    const float* rel_l_A = (const float*)d_in[11];
    const float* rel_r_A = (const float*)d_in[12];
    const float* rel_l_B = (const float*)d_in[13];
    const float* rel_r_B = (const float*)d_in[14];
    float* out = (float*)d_out;

    void *p_relBA, *p_relAA, *p_relAB, *p_dBA, *p_dAA, *p_dAB, *p_hA, *p_hB;
    void *p_al0, *p_ar0, *p_al1, *p_ar1, *p_al2, *p_ar2;
    cudaGetSymbolAddress(&p_relBA, g_relBA);
    cudaGetSymbolAddress(&p_relAA, g_relAA);
    cudaGetSymbolAddress(&p_relAB, g_relAB);
    cudaGetSymbolAddress(&p_dBA, g_dBA);
    cudaGetSymbolAddress(&p_dAA, g_dAA);
    cudaGetSymbolAddress(&p_dAB, g_dAB);
    cudaGetSymbolAddress(&p_hA, g_hA);
    cudaGetSymbolAddress(&p_hB, g_hB);
    cudaGetSymbolAddress(&p_al0, g_al0);
    cudaGetSymbolAddress(&p_ar0, g_ar0);
    cudaGetSymbolAddress(&p_al1, g_al1);
    cudaGetSymbolAddress(&p_ar1, g_ar1);
    cudaGetSymbolAddress(&p_al2, g_al2);
    cudaGetSymbolAddress(&p_ar2, g_ar2);

    cudaMemsetAsync(p_relBA, 0, sizeof(float) * NNA * DD, 0);
    cudaMemsetAsync(p_relAA, 0, sizeof(float) * NNA * DD, 0);
    cudaMemsetAsync(p_relAB, 0, sizeof(float) * NNB * DD, 0);
    cudaMemsetAsync(p_dBA, 0, sizeof(float) * NNA * HH, 0);
    cudaMemsetAsync(p_dAA, 0, sizeof(float) * NNA * HH, 0);
    cudaMemsetAsync(p_dAB, 0, sizeof(float) * NNB * HH, 0);

    float* hA  = (float*)p_hA;
    float* hB  = (float*)p_hB;
    float* al0 = (float*)p_al0; float* ar0 = (float*)p_ar0;
    float* al1 = (float*)p_al1; float* ar1 = (float*)p_ar1;
    float* al2 = (float*)p_al2; float* ar2 = (float*)p_ar2;

    // 1) projections (tensor-core bf16x3 split GEMM)
    {
        dim3 grid((NNA + 127) / 128, 4);
        gemm_bf16x3<<<grid, 256>>>(x_A, W_A, b_A, hA, NNA);
        gemm_bf16x3<<<grid, 256>>>(x_B, W_B, b_B, hB, NNB);
    }

    // 2) node alphas
    {
        int g = (NNA * 8 + 255) / 256;
        alphas2_kernel<4><<<g, 256>>>(hA, NNA,
                                      attn_l + 0 * 256, attn_r + 1 * 256,
                                      attn_l + 2 * 256, attn_r + 2 * 256,
                                      al0, ar1, al2, ar2);
        alphas2_kernel<2><<<g, 256>>>(hB, NNB,
                                      attn_r + 0 * 256, attn_l + 1 * 256,
                                      (const float*)0, (const float*)0,
                                      ar0, al1, (float*)0, (float*)0);
    }

    // 3) single edge pass per relation: exp + denom + message scatter
    {
        int g = (EED * 32 + 255) / 256;  // one warp per edge
        edge_msg_kernel<<<g, 256>>>(e_ba, EED, al1, ar1, (float*)p_dBA, hB, (float*)p_relBA);
        edge_msg_kernel<<<g, 256>>>(e_aa, EED, al2, ar2, (float*)p_dAA, hA, (float*)p_relAA);
        edge_msg_kernel<<<g, 256>>>(e_ab, EED, al0, ar0, (float*)p_dAB, hA, (float*)p_relAB);
    }

    // 4) beta combine + relu -> output
    beta_A_kernel<<<NNA, 256>>>(hA, (float*)p_relBA, (float*)p_dBA,
                                (float*)p_relAA, (float*)p_dAA,
                                rel_l_A, rel_r_A, out, NNA);
    beta_B_kernel<<<NNB, 256>>>(hB, (float*)p_relAB, (float*)p_dAB,
                                rel_l_B, rel_r_B, out + (size_t)NNA * 256, NNB);

    (void)in_sizes; (void)n_in; (void)out_size;
}

// round 3
// speedup vs baseline: 1.8078x; 1.3645x over previous
#include <cuda_runtime.h>
#include <cuda_bf16.h>
#include <math.h>
#include <stdint.h>

// Problem constants (fixed shapes per reference)
#define NNA 40000
#define NNB 40000
#define EED 400000
#define DD  256
#define HH  8

// ---------------- scratch (static device globals; no allocation) ----------------
__device__ float g_hA[NNA * DD];
__device__ float g_hB[NNB * DD];
__device__ float g_relBA[NNA * DD];   // normalized aggregated messages
__device__ float g_relAA[NNA * DD];
__device__ float g_relAB[NNB * DD];
__device__ float g_al0[NNA * HH];
__device__ float g_ar0[NNB * HH];
__device__ float g_al1[NNB * HH];
__device__ float g_ar1[NNA * HH];
__device__ float g_al2[NNA * HH];
__device__ float g_ar2[NNA * HH];
__device__ float g_blA[NNA * HH];     // h_A . rel_l_A  (beta left term)
__device__ float g_blB[NNB * HH];     // h_B . rel_l_B
__device__ int   g_srcs[3 * EED];     // dst-sorted src indices per relation
__device__ int   g_cnt[3 * NNA];      // degree counts -> cursors after scan
__device__ int   g_rowptr[3 * (NNA + 1)];

// ---------------- helpers ----------------
__device__ __forceinline__ float warp_sum(float v) {
#pragma unroll
    for (int o = 16; o; o >>= 1) v += __shfl_xor_sync(0xffffffffu, v, o);
    return v;
}
__device__ __forceinline__ float leaky02(float x) { return x > 0.f ? x : 0.2f * x; }

__device__ __forceinline__ uint32_t smem_u32(const void* p) {
    uint32_t a;
    asm("{ .reg .u64 t; cvta.to.shared.u64 t, %1; cvt.u32.u64 %0, t; }" : "=r"(a) : "l"(p));
    return a;
}
__device__ __forceinline__ void ldsm4(uint32_t* r, uint32_t a) {
    asm volatile("ldmatrix.sync.aligned.m8n8.x4.shared.b16 {%0,%1,%2,%3}, [%4];"
                 : "=r"(r[0]), "=r"(r[1]), "=r"(r[2]), "=r"(r[3]) : "r"(a));
}
__device__ __forceinline__ void ldsm4t(uint32_t* r, uint32_t a) {
    asm volatile("ldmatrix.sync.aligned.m8n8.x4.trans.shared.b16 {%0,%1,%2,%3}, [%4];"
                 : "=r"(r[0]), "=r"(r[1]), "=r"(r[2]), "=r"(r[3]) : "r"(a));
}
__device__ __forceinline__ void mma16816(float* d, const uint32_t* a, uint32_t b0, uint32_t b1) {
    asm volatile("mma.sync.aligned.m16n8k16.row.col.f32.bf16.bf16.f32 "
                 "{%0,%1,%2,%3}, {%4,%5,%6,%7}, {%8,%9}, {%0,%1,%2,%3};"
                 : "+f"(d[0]), "+f"(d[1]), "+f"(d[2]), "+f"(d[3])
                 : "r"(a[0]), "r"(a[1]), "r"(a[2]), "r"(a[3]), "r"(b0), "r"(b1));
}
__device__ __forceinline__ void split_pair(float a, float b, uint32_t& hi, uint32_t& lo) {
    __nv_bfloat16 ah = __float2bfloat16(a);
    __nv_bfloat16 bh = __float2bfloat16(b);
    __nv_bfloat16 al = __float2bfloat16(a - __bfloat162float(ah));
    __nv_bfloat16 bl = __float2bfloat16(b - __bfloat162float(bh));
    __nv_bfloat162 H; H.x = ah; H.y = bh;
    __nv_bfloat162 L; L.x = al; L.y = bl;
    hi = *reinterpret_cast<uint32_t*>(&H);
    lo = *reinterpret_cast<uint32_t*>(&L);
}

// ---------------- GEMM + fused per-node dot products ------------------------------
// C[M,256] = A[M,256] @ W[256,256] + bias (bf16x3 split, tensor cores).
// CTA tile 128x64 (exactly 2 heads of 32 cols), 256 thr, warps 2(m) x 4(n).
// Epilogue also computes, for up to 5 vectors v[256]: o[n,h] = sum_c h[n,h,c]*v[h,c].
#define ASTR 40
#define BSTR 72
__global__ __launch_bounds__(256)
void gemm_fused(const float* __restrict__ A, const float* __restrict__ W,
                const float* __restrict__ bias, float* __restrict__ C, int M,
                const float* __restrict__ v0, const float* __restrict__ v1,
                const float* __restrict__ v2, const float* __restrict__ v3,
                const float* __restrict__ v4,
                float* __restrict__ o0, float* __restrict__ o1,
                float* __restrict__ o2, float* __restrict__ o3,
                float* __restrict__ o4) {
    __shared__ __nv_bfloat16 sAhi[128 * ASTR];
    __shared__ __nv_bfloat16 sAlo[128 * ASTR];
    __shared__ __nv_bfloat16 sBhi[32 * BSTR];
    __shared__ __nv_bfloat16 sBlo[32 * BSTR];
    __shared__ float sattn[5][64];
    __shared__ float sbias[64];
    __shared__ float spart[4][128];

    const int tid  = threadIdx.x;
    const int lane = tid & 31;
    const int wid  = tid >> 5;
    const int wm   = wid & 1;
    const int wn   = wid >> 1;
    const int row0 = blockIdx.x * 128;
    const int col0 = blockIdx.y * 64;

    const float* vp[5] = {v0, v1, v2, v3, v4};
    float* op[5] = {o0, o1, o2, o3, o4};
    if (tid < 64) sbias[tid] = __ldg(bias + col0 + tid);
#pragma unroll
    for (int v = 0; v < 5; v++)
        if (vp[v] && tid < 64) sattn[v][tid] = __ldg(vp[v] + col0 + tid);

    float acc[4][2][4];
#pragma unroll
    for (int i = 0; i < 4; i++)
#pragma unroll
        for (int j = 0; j < 2; j++)
#pragma unroll
            for (int k = 0; k < 4; k++) acc[i][j][k] = 0.f;

    float4 av[4], bv[2];
#pragma unroll
    for (int p = 0; p < 4; p++) {
        int f = tid + 256 * p, r = f >> 3, c = (f & 7) * 4;
        int gr = row0 + r;
        av[p] = (gr < M) ? __ldg((const float4*)(A + (size_t)gr * 256 + c))
                         : make_float4(0.f, 0.f, 0.f, 0.f);
    }
#pragma unroll
    for (int p = 0; p < 2; p++) {
        int f = tid + 256 * p, r = f >> 4, c = (f & 15) * 4;
        bv[p] = __ldg((const float4*)(W + (size_t)r * 256 + col0 + c));
    }

    for (int kb = 0; kb < 8; kb++) {
#pragma unroll
        for (int p = 0; p < 4; p++) {
            int f = tid + 256 * p, r = f >> 3, c = (f & 7) * 4;
            uint32_t h01, l01, h23, l23;
            split_pair(av[p].x, av[p].y, h01, l01);
            split_pair(av[p].z, av[p].w, h23, l23);
            *(uint2*)&sAhi[r * ASTR + c] = make_uint2(h01, h23);
            *(uint2*)&sAlo[r * ASTR + c] = make_uint2(l01, l23);
        }
#pragma unroll
        for (int p = 0; p < 2; p++) {
            int f = tid + 256 * p, r = f >> 4, c = (f & 15) * 4;
            uint32_t h01, l01, h23, l23;
            split_pair(bv[p].x, bv[p].y, h01, l01);
            split_pair(bv[p].z, bv[p].w, h23, l23);
            *(uint2*)&sBhi[r * BSTR + c] = make_uint2(h01, h23);
            *(uint2*)&sBlo[r * BSTR + c] = make_uint2(l01, l23);
        }
        __syncthreads();

        if (kb < 7) {
            int k0 = (kb + 1) * 32;
#pragma unroll
            for (int p = 0; p < 4; p++) {
                int f = tid + 256 * p, r = f >> 3, c = (f & 7) * 4;
                int gr = row0 + r;
                av[p] = (gr < M) ? __ldg((const float4*)(A + (size_t)gr * 256 + k0 + c))
                                 : make_float4(0.f, 0.f, 0.f, 0.f);
            }
#pragma unroll
            for (int p = 0; p < 2; p++) {
                int f = tid + 256 * p, r = f >> 4, c = (f & 15) * 4;
                bv[p] = __ldg((const float4*)(W + (size_t)(k0 + r) * 256 + col0 + c));
            }
        }

#pragma unroll
        for (int kk = 0; kk < 32; kk += 16) {
            uint32_t ahi[4][4], alo[4][4], bh[4], bl[4];
            int arow = wm * 64 + (lane & 15);
            int acol = kk + ((lane >> 4) << 3);
#pragma unroll
            for (int mt = 0; mt < 4; mt++)
                ldsm4(ahi[mt], smem_u32(&sAhi[(arow + mt * 16) * ASTR + acol]));
            {
                int brow = kk + (lane & 7) + ((lane >> 3) & 1) * 8;
                int bcol = wn * 16 + ((lane >> 4) << 3);
                ldsm4t(bh, smem_u32(&sBhi[brow * BSTR + bcol]));
                ldsm4t(bl, smem_u32(&sBlo[brow * BSTR + bcol]));
            }
#pragma unroll
            for (int mt = 0; mt < 4; mt++)
                ldsm4(alo[mt], smem_u32(&sAlo[(arow + mt * 16) * ASTR + acol]));

#pragma unroll
            for (int mt = 0; mt < 4; mt++)
#pragma unroll
                for (int nt = 0; nt < 2; nt++) {
                    mma16816(acc[mt][nt], ahi[mt], bh[nt * 2], bh[nt * 2 + 1]);
                    mma16816(acc[mt][nt], ahi[mt], bl[nt * 2], bl[nt * 2 + 1]);
                    mma16816(acc[mt][nt], alo[mt], bh[nt * 2], bh[nt * 2 + 1]);
                }
        }
        __syncthreads();
    }

    // ---- epilogue: add bias into acc, store C ----
#pragma unroll
    for (int mt = 0; mt < 4; mt++)
#pragma unroll
        for (int nt = 0; nt < 2; nt++) {
            int cl = wn * 16 + nt * 8 + (lane & 3) * 2;
#pragma unroll
            for (int half = 0; half < 2; half++) {
                acc[mt][nt][half * 2 + 0] += sbias[cl + 0];
                acc[mt][nt][half * 2 + 1] += sbias[cl + 1];
            }
        }
#pragma unroll
    for (int mt = 0; mt < 4; mt++)
#pragma unroll
        for (int half = 0; half < 2; half++) {
            int gr = row0 + wm * 64 + mt * 16 + (lane >> 2) + half * 8;
            if (gr < M) {
#pragma unroll
                for (int nt = 0; nt < 2; nt++) {
                    int gc = col0 + wn * 16 + nt * 8 + (lane & 3) * 2;
                    float2 o;
                    o.x = acc[mt][nt][half * 2 + 0];
                    o.y = acc[mt][nt][half * 2 + 1];
                    *(float2*)(C + (size_t)gr * 256 + gc) = o;
                }
            }
        }

    // ---- fused per-node dots: reduce acc over the 64 tile cols ----
#pragma unroll
    for (int v = 0; v < 5; v++) {
        if (!vp[v]) continue;
        __syncthreads();
#pragma unroll
        for (int mt = 0; mt < 4; mt++)
#pragma unroll
            for (int half = 0; half < 2; half++) {
                float p = 0.f;
#pragma unroll
                for (int nt = 0; nt < 2; nt++) {
                    int cl = wn * 16 + nt * 8 + (lane & 3) * 2;
                    p = fmaf(acc[mt][nt][half * 2 + 0], sattn[v][cl + 0], p);
                    p = fmaf(acc[mt][nt][half * 2 + 1], sattn[v][cl + 1], p);
                }
                p += __shfl_xor_sync(0xffffffffu, p, 1);
                p += __shfl_xor_sync(0xffffffffu, p, 2);
                if ((lane & 3) == 0)
                    spart[wn][wm * 64 + mt * 16 + (lane >> 2) + half * 8] = p;
            }
        __syncthreads();
        {
            int row = tid >> 1, j = tid & 1;
            int gr = row0 + row;
            if (gr < M)
                op[v][(size_t)gr * 8 + blockIdx.y * 2 + j] =
                    spart[2 * j][row] + spart[2 * j + 1][row];
        }
    }
}

// ---------------- counting sort by dst ----------------
__global__ __launch_bounds__(256)
void count_kernel(const int* __restrict__ edge, int E, int* __restrict__ cnt) {
    int t = blockIdx.x * 256 + threadIdx.x;
    if (t < E) atomicAdd(&cnt[__ldg(edge + E + t)], 1);
}

// one block per relation; N = 40000, CH = 40, 1024 threads
__global__ __launch_bounds__(1024)
void scan_kernel(int* __restrict__ cnt, int* __restrict__ rowptr) {
    __shared__ int part[1024];
    const int N = NNA, CH = 40;
    int* c  = cnt + blockIdx.x * N;
    int* rp = rowptr + blockIdx.x * (N + 1);
    int t = threadIdx.x;
    int s = 0;
#pragma unroll 4
    for (int j = 0; j < CH; j++) {
        int i = t * CH + j;
        if (i < N) s += c[i];
    }
    part[t] = s;
    __syncthreads();
    for (int off = 1; off < 1024; off <<= 1) {
        int v = (t >= off) ? part[t - off] : 0;
        __syncthreads();
        part[t] += v;
        __syncthreads();
    }
    int excl = (t == 0) ? 0 : part[t - 1];
    for (int j = 0; j < CH; j++) {
        int i = t * CH + j;
        if (i < N) {
            rp[i] = excl;
            int v = c[i];
            c[i] = excl;      // becomes scatter cursor
            excl += v;
        }
    }
    if (t == 1023) rp[N] = excl;
}

__global__ __launch_bounds__(256)
void scatter_kernel(const int* __restrict__ edge, int E,
                    int* __restrict__ cursor, int* __restrict__ srcs) {
    int t = blockIdx.x * 256 + threadIdx.x;
    if (t >= E) return;
    int dst = __ldg(edge + E + t);
    int pos = atomicAdd(&cursor[dst], 1);
    srcs[pos] = __ldg(edge + t);
}

// ---------------- CSR aggregation: warp per dst, normalized output ----------------
__global__ __launch_bounds__(256)
void agg_kernel(const int* __restrict__ srcs, const int* __restrict__ rowptr,
                const float* __restrict__ al, const float* __restrict__ ar,
                const float* __restrict__ h, float* __restrict__ rel, int N) {
    int w = (blockIdx.x * 256 + threadIdx.x) >> 5;
    int lane = threadIdx.x & 31;
    if (w >= N) return;
    int head = lane >> 2;
    int start = __ldg(rowptr + w);
    int end   = __ldg(rowptr + w + 1);
    float arh = __ldg(ar + w * 8 + head);

    float4 a0 = make_float4(0.f, 0.f, 0.f, 0.f);
    float4 a1 = make_float4(0.f, 0.f, 0.f, 0.f);
    float den = 0.f;

    for (int base = start; base < end; base += 32) {
        int n = min(32, end - base);
        int mysrc = (base + lane < end) ? __ldg(srcs + base + lane) : 0;
        for (int i = 0; i < n; i++) {
            int src = __shfl_sync(0xffffffffu, mysrc, i);
            float ex = __expf(leaky02(__ldg(al + src * 8 + head) + arh));
            den += ex;
            const float4* hs = (const float4*)(h + (size_t)src * 256);
            float4 v0 = __ldg(hs + lane * 2);
            float4 v1 = __ldg(hs + lane * 2 + 1);
            a0.x = fmaf(ex, v0.x, a0.x); a0.y = fmaf(ex, v0.y, a0.y);
            a0.z = fmaf(ex, v0.z, a0.z); a0.w = fmaf(ex, v0.w, a0.w);
            a1.x = fmaf(ex, v1.x, a1.x); a1.y = fmaf(ex, v1.y, a1.y);
            a1.z = fmaf(ex, v1.z, a1.z); a1.w = fmaf(ex, v1.w, a1.w);
        }
    }
    float inv = den > 0.f ? 1.f / den : 0.f;
    a0.x *= inv; a0.y *= inv; a0.z *= inv; a0.w *= inv;
    a1.x *= inv; a1.y *= inv; a1.z *= inv; a1.w *= inv;
    float4* rp = (float4*)(rel + (size_t)w * 256);
    rp[lane * 2]     = a0;
    rp[lane * 2 + 1] = a1;
}

// ---------------- beta combine (rel pre-normalized, bl precomputed) --------------
__global__ __launch_bounds__(256)
void beta_A_kernel(const float* __restrict__ h,
                   const float* __restrict__ rel0, const float* __restrict__ rel1,
                   const float* __restrict__ blv, const float* __restrict__ rel_r,
                   float* __restrict__ out, int N) {
    int n = blockIdx.x;
    if (n >= N) return;
    int hh   = threadIdx.x >> 5;
    int lane = threadIdx.x & 31;
    size_t idx = (size_t)n * 256 + hh * 32 + lane;

    float x  = h[idx];
    float e0 = rel0[idx];
    float e1 = rel1[idx];
    float rr = rel_r[hh * 32 + lane];
    float bl = blv[n * 8 + hh];
    float b0 = warp_sum(e0 * rr);
    float b1 = warp_sum(e1 * rr);
    float b2 = warp_sum(x * rr);

    float s0 = leaky02(bl + b0);
    float s1 = leaky02(bl + b1);
    float s2 = leaky02(bl + b2);
    float mx = fmaxf(s0, fmaxf(s1, s2));
    float w0 = __expf(s0 - mx), w1 = __expf(s1 - mx), w2 = __expf(s2 - mx);
    float inv = 1.f / (w0 + w1 + w2);
    float o = (e0 * w0 + e1 * w1 + x * w2) * inv;
    out[idx] = fmaxf(o, 0.f);
}

__global__ __launch_bounds__(256)
void beta_B_kernel(const float* __restrict__ h,
                   const float* __restrict__ rel0,
                   const float* __restrict__ blv, const float* __restrict__ rel_r,
                   float* __restrict__ out, int N) {
    int n = blockIdx.x;
    if (n >= N) return;
    int hh   = threadIdx.x >> 5;
    int lane = threadIdx.x & 31;
    size_t idx = (size_t)n * 256 + hh * 32 + lane;

    float x  = h[idx];
    float e0 = rel0[idx];
    float rr = rel_r[hh * 32 + lane];
    float bl = blv[n * 8 + hh];
    float b0 = warp_sum(e0 * rr);
    float b1 = warp_sum(x * rr);

    float s0 = leaky02(bl + b0);
    float s1 = leaky02(bl + b1);
    float mx = fmaxf(s0, s1);
    float w0 = __expf(s0 - mx), w1 = __expf(s1 - mx);
    float inv = 1.f / (w0 + w1);
    float o = (e0 * w0 + x * w1) * inv;
    out[idx] = fmaxf(o, 0.f);
}

// ---------------- launch ----------------
extern "C" void kernel_launch(void* const* d_in, const int* in_sizes, int n_in,
                              void* d_out, int out_size) {
    const float* x_A     = (const float*)d_in[0];
    const float* x_B     = (const float*)d_in[1];
    const int*   e_ab    = (const int*)d_in[2];
    const int*   e_ba    = (const int*)d_in[3];
    const int*   e_aa    = (const int*)d_in[4];
    const float* W_A     = (const float*)d_in[5];
    const float* b_A     = (const float*)d_in[6];
    const float* W_B     = (const float*)d_in[7];
    const float* b_B     = (const float*)d_in[8];
    const float* attn_l  = (const float*)d_in[9];   // [3,8,32]
    const float* attn_r  = (const float*)d_in[10];
    const float* rel_l_A = (const float*)d_in[11];
    const float* rel_r_A = (const float*)d_in[12];
    const float* rel_l_B = (const float*)d_in[13];
    const float* rel_r_B = (const float*)d_in[14];
    float* out = (float*)d_out;

    void *p_relBA, *p_relAA, *p_relAB, *p_hA, *p_hB;
    void *p_al0, *p_ar0, *p_al1, *p_ar1, *p_al2, *p_ar2, *p_blA, *p_blB;
    void *p_srcs, *p_cnt, *p_rowptr;
    cudaGetSymbolAddress(&p_relBA, g_relBA);
    cudaGetSymbolAddress(&p_relAA, g_relAA);
    cudaGetSymbolAddress(&p_relAB, g_relAB);
    cudaGetSymbolAddress(&p_hA, g_hA);
    cudaGetSymbolAddress(&p_hB, g_hB);
    cudaGetSymbolAddress(&p_al0, g_al0);
    cudaGetSymbolAddress(&p_ar0, g_ar0);
    cudaGetSymbolAddress(&p_al1, g_al1);
    cudaGetSymbolAddress(&p_ar1, g_ar1);
    cudaGetSymbolAddress(&p_al2, g_al2);
    cudaGetSymbolAddress(&p_ar2, g_ar2);
    cudaGetSymbolAddress(&p_blA, g_blA);
    cudaGetSymbolAddress(&p_blB, g_blB);
    cudaGetSymbolAddress(&p_srcs, g_srcs);
    cudaGetSymbolAddress(&p_cnt, g_cnt);
    cudaGetSymbolAddress(&p_rowptr, g_rowptr);

    float* hA  = (float*)p_hA;
    float* hB  = (float*)p_hB;
    int* cnt    = (int*)p_cnt;
    int* rowptr = (int*)p_rowptr;
    int* srcs   = (int*)p_srcs;

    cudaMemsetAsync(cnt, 0, sizeof(int) * 3 * NNA, 0);

    // 1) projections with fused per-node dots
    {
        dim3 grid((NNA + 127) / 128, 4);
        gemm_fused<<<grid, 256>>>(x_A, W_A, b_A, hA, NNA,
                                  attn_l + 0 * 256, attn_r + 1 * 256,
                                  attn_l + 2 * 256, attn_r + 2 * 256, rel_l_A,
                                  (float*)p_al0, (float*)p_ar1,
                                  (float*)p_al2, (float*)p_ar2, (float*)p_blA);
        gemm_fused<<<grid, 256>>>(x_B, W_B, b_B, hB, NNB,
                                  attn_r + 0 * 256, attn_l + 1 * 256,
                                  (const float*)0, (const float*)0, rel_l_B,
                                  (float*)p_ar0, (float*)p_al1,
                                  (float*)0, (float*)0, (float*)p_blB);
    }

    // 2) counting sort of edges by dst (3 relations; order: BA, AA, AB)
    {
        int g = (EED + 255) / 256;
        count_kernel<<<g, 256>>>(e_ba, EED, cnt + 0 * NNA);
        count_kernel<<<g, 256>>>(e_aa, EED, cnt + 1 * NNA);
        count_kernel<<<g, 256>>>(e_ab, EED, cnt + 2 * NNA);
        scan_kernel<<<3, 1024>>>(cnt, rowptr);
        scatter_kernel<<<g, 256>>>(e_ba, EED, cnt + 0 * NNA, srcs + 0 * EED);
        scatter_kernel<<<g, 256>>>(e_aa, EED, cnt + 1 * NNA, srcs + 1 * EED);
        scatter_kernel<<<g, 256>>>(e_ab, EED, cnt + 2 * NNA, srcs + 2 * EED);
    }

    // 3) CSR aggregation (normalized)
    {
        int g = (NNA * 32 + 255) / 256;
        agg_kernel<<<g, 256>>>(srcs + 0 * EED, rowptr + 0 * (NNA + 1),
                               (float*)p_al1, (float*)p_ar1, hB, (float*)p_relBA, NNA);
        agg_kernel<<<g, 256>>>(srcs + 1 * EED, rowptr + 1 * (NNA + 1),
                               (float*)p_al2, (float*)p_ar2, hA, (float*)p_relAA, NNA);
        agg_kernel<<<g, 256>>>(srcs + 2 * EED, rowptr + 2 * (NNA + 1),
                               (float*)p_al0, (float*)p_ar0, hA, (float*)p_relAB, NNB);
    }

    // 4) beta combine + relu -> output
    beta_A_kernel<<<NNA, 256>>>(hA, (float*)p_relBA, (float*)p_relAA,
                                (float*)p_blA, rel_r_A, out, NNA);
    beta_B_kernel<<<NNB, 256>>>(hB, (float*)p_relAB,
                                (float*)p_blB, rel_r_B, out + (size_t)NNA * 256, NNB);

    (void)in_sizes; (void)n_in; (void)out_size;
}

// round 4
// speedup vs baseline: 1.9464x; 1.0767x over previous
#include <cuda_runtime.h>
#include <cuda_bf16.h>
#include <cuda_fp16.h>
#include <math.h>
#include <stdint.h>

// Problem constants (fixed shapes per reference)
#define NNA 40000
#define NNB 40000
#define EED 400000
#define DD  256
#define HH  8

// ---------------- scratch (static device globals; no allocation) ----------------
__device__ float  g_hA[NNA * DD];
__device__ float  g_hB[NNB * DD];
__device__ __half g_hA16[NNA * DD];
__device__ __half g_hB16[NNB * DD];
__device__ __half g_relBA[NNA * DD];   // normalized aggregated messages (fp16)
__device__ __half g_relAA[NNA * DD];
__device__ __half g_relAB[NNB * DD];
__device__ float  g_al0[NNA * HH];
__device__ float  g_ar0[NNB * HH];
__device__ float  g_al1[NNB * HH];
__device__ float  g_ar1[NNA * HH];
__device__ float  g_al2[NNA * HH];
__device__ float  g_ar2[NNA * HH];
__device__ float  g_blA[NNA * HH];
__device__ float  g_blB[NNB * HH];
__device__ int    g_srcs[3 * EED];
__device__ int    g_cnt[3 * NNA];
__device__ int    g_rowptr[3 * (NNA + 1)];

// ---------------- helpers ----------------
__device__ __forceinline__ float warp_sum(float v) {
#pragma unroll
    for (int o = 16; o; o >>= 1) v += __shfl_xor_sync(0xffffffffu, v, o);
    return v;
}
__device__ __forceinline__ float leaky02(float x) { return x > 0.f ? x : 0.2f * x; }

__device__ __forceinline__ uint32_t smem_u32(const void* p) {
    uint32_t a;
    asm("{ .reg .u64 t; cvta.to.shared.u64 t, %1; cvt.u32.u64 %0, t; }" : "=r"(a) : "l"(p));
    return a;
}
__device__ __forceinline__ void ldsm4(uint32_t* r, uint32_t a) {
    asm volatile("ldmatrix.sync.aligned.m8n8.x4.shared.b16 {%0,%1,%2,%3}, [%4];"
                 : "=r"(r[0]), "=r"(r[1]), "=r"(r[2]), "=r"(r[3]) : "r"(a));
}
__device__ __forceinline__ void ldsm4t(uint32_t* r, uint32_t a) {
    asm volatile("ldmatrix.sync.aligned.m8n8.x4.trans.shared.b16 {%0,%1,%2,%3}, [%4];"
                 : "=r"(r[0]), "=r"(r[1]), "=r"(r[2]), "=r"(r[3]) : "r"(a));
}
__device__ __forceinline__ void mma16816(float* d, const uint32_t* a, uint32_t b0, uint32_t b1) {
    asm volatile("mma.sync.aligned.m16n8k16.row.col.f32.bf16.bf16.f32 "
                 "{%0,%1,%2,%3}, {%4,%5,%6,%7}, {%8,%9}, {%0,%1,%2,%3};"
                 : "+f"(d[0]), "+f"(d[1]), "+f"(d[2]), "+f"(d[3])
                 : "r"(a[0]), "r"(a[1]), "r"(a[2]), "r"(a[3]), "r"(b0), "r"(b1));
}
__device__ __forceinline__ void split_pair(float a, float b, uint32_t& hi, uint32_t& lo) {
    __nv_bfloat16 ah = __float2bfloat16(a);
    __nv_bfloat16 bh = __float2bfloat16(b);
    __nv_bfloat16 al = __float2bfloat16(a - __bfloat162float(ah));
    __nv_bfloat16 bl = __float2bfloat16(b - __bfloat162float(bh));
    __nv_bfloat162 H; H.x = ah; H.y = bh;
    __nv_bfloat162 L; L.x = al; L.y = bl;
    hi = *reinterpret_cast<uint32_t*>(&H);
    lo = *reinterpret_cast<uint32_t*>(&L);
}

// ---------------- GEMM + fused per-node dot products ------------------------------
// C[M,256] = A[M,256] @ W[256,256] + bias (bf16x3 split, tensor cores).
// Also writes C16 (fp16 copy) and, for up to 5 vectors v[256]:
//   o[n,h] = sum_c h[n,h,c]*v[h,c].
#define ASTR 40
#define BSTR 72
__global__ __launch_bounds__(256)
void gemm_fused(const float* __restrict__ A, const float* __restrict__ W,
                const float* __restrict__ bias, float* __restrict__ C,
                __half* __restrict__ C16, int M,
                const float* __restrict__ v0, const float* __restrict__ v1,
                const float* __restrict__ v2, const float* __restrict__ v3,
                const float* __restrict__ v4,
                float* __restrict__ o0, float* __restrict__ o1,
                float* __restrict__ o2, float* __restrict__ o3,
                float* __restrict__ o4) {
    __shared__ __nv_bfloat16 sAhi[128 * ASTR];
    __shared__ __nv_bfloat16 sAlo[128 * ASTR];
    __shared__ __nv_bfloat16 sBhi[32 * BSTR];
    __shared__ __nv_bfloat16 sBlo[32 * BSTR];
    __shared__ float sattn[5][64];
    __shared__ float sbias[64];
    __shared__ float spart[4][128];

    const int tid  = threadIdx.x;
    const int lane = tid & 31;
    const int wid  = tid >> 5;
    const int wm   = wid & 1;
    const int wn   = wid >> 1;
    const int row0 = blockIdx.x * 128;
    const int col0 = blockIdx.y * 64;

    const float* vp[5] = {v0, v1, v2, v3, v4};
    float* op[5] = {o0, o1, o2, o3, o4};
    if (tid < 64) sbias[tid] = __ldg(bias + col0 + tid);
#pragma unroll
    for (int v = 0; v < 5; v++)
        if (vp[v] && tid < 64) sattn[v][tid] = __ldg(vp[v] + col0 + tid);

    float acc[4][2][4];
#pragma unroll
    for (int i = 0; i < 4; i++)
#pragma unroll
        for (int j = 0; j < 2; j++)
#pragma unroll
            for (int k = 0; k < 4; k++) acc[i][j][k] = 0.f;

    float4 av[4], bv[2];
#pragma unroll
    for (int p = 0; p < 4; p++) {
        int f = tid + 256 * p, r = f >> 3, c = (f & 7) * 4;
        int gr = row0 + r;
        av[p] = (gr < M) ? __ldg((const float4*)(A + (size_t)gr * 256 + c))
                         : make_float4(0.f, 0.f, 0.f, 0.f);
    }
#pragma unroll
    for (int p = 0; p < 2; p++) {
        int f = tid + 256 * p, r = f >> 4, c = (f & 15) * 4;
        bv[p] = __ldg((const float4*)(W + (size_t)r * 256 + col0 + c));
    }

    for (int kb = 0; kb < 8; kb++) {
#pragma unroll
        for (int p = 0; p < 4; p++) {
            int f = tid + 256 * p, r = f >> 3, c = (f & 7) * 4;
            uint32_t h01, l01, h23, l23;
            split_pair(av[p].x, av[p].y, h01, l01);
            split_pair(av[p].z, av[p].w, h23, l23);
            *(uint2*)&sAhi[r * ASTR + c] = make_uint2(h01, h23);
            *(uint2*)&sAlo[r * ASTR + c] = make_uint2(l01, l23);
        }
#pragma unroll
        for (int p = 0; p < 2; p++) {
            int f = tid + 256 * p, r = f >> 4, c = (f & 15) * 4;
            uint32_t h01, l01, h23, l23;
            split_pair(bv[p].x, bv[p].y, h01, l01);
            split_pair(bv[p].z, bv[p].w, h23, l23);
            *(uint2*)&sBhi[r * BSTR + c] = make_uint2(h01, h23);
            *(uint2*)&sBlo[r * BSTR + c] = make_uint2(l01, l23);
        }
        __syncthreads();

        if (kb < 7) {
            int k0 = (kb + 1) * 32;
#pragma unroll
            for (int p = 0; p < 4; p++) {
                int f = tid + 256 * p, r = f >> 3, c = (f & 7) * 4;
                int gr = row0 + r;
                av[p] = (gr < M) ? __ldg((const float4*)(A + (size_t)gr * 256 + k0 + c))
                                 : make_float4(0.f, 0.f, 0.f, 0.f);
            }
#pragma unroll
            for (int p = 0; p < 2; p++) {
                int f = tid + 256 * p, r = f >> 4, c = (f & 15) * 4;
                bv[p] = __ldg((const float4*)(W + (size_t)(k0 + r) * 256 + col0 + c));
            }
        }

#pragma unroll
        for (int kk = 0; kk < 32; kk += 16) {
            uint32_t ahi[4][4], alo[4][4], bh[4], bl[4];
            int arow = wm * 64 + (lane & 15);
            int acol = kk + ((lane >> 4) << 3);
#pragma unroll
            for (int mt = 0; mt < 4; mt++)
                ldsm4(ahi[mt], smem_u32(&sAhi[(arow + mt * 16) * ASTR + acol]));
            {
                int brow = kk + (lane & 7) + ((lane >> 3) & 1) * 8;
                int bcol = wn * 16 + ((lane >> 4) << 3);
                ldsm4t(bh, smem_u32(&sBhi[brow * BSTR + bcol]));
                ldsm4t(bl, smem_u32(&sBlo[brow * BSTR + bcol]));
            }
#pragma unroll
            for (int mt = 0; mt < 4; mt++)
                ldsm4(alo[mt], smem_u32(&sAlo[(arow + mt * 16) * ASTR + acol]));

#pragma unroll
            for (int mt = 0; mt < 4; mt++)
#pragma unroll
                for (int nt = 0; nt < 2; nt++) {
                    mma16816(acc[mt][nt], ahi[mt], bh[nt * 2], bh[nt * 2 + 1]);
                    mma16816(acc[mt][nt], ahi[mt], bl[nt * 2], bl[nt * 2 + 1]);
                    mma16816(acc[mt][nt], alo[mt], bh[nt * 2], bh[nt * 2 + 1]);
                }
        }
        __syncthreads();
    }

    // ---- epilogue: bias, store fp32 + fp16 copies ----
#pragma unroll
    for (int mt = 0; mt < 4; mt++)
#pragma unroll
        for (int nt = 0; nt < 2; nt++) {
            int cl = wn * 16 + nt * 8 + (lane & 3) * 2;
#pragma unroll
            for (int half = 0; half < 2; half++) {
                acc[mt][nt][half * 2 + 0] += sbias[cl + 0];
                acc[mt][nt][half * 2 + 1] += sbias[cl + 1];
            }
        }
#pragma unroll
    for (int mt = 0; mt < 4; mt++)
#pragma unroll
        for (int half = 0; half < 2; half++) {
            int gr = row0 + wm * 64 + mt * 16 + (lane >> 2) + half * 8;
            if (gr < M) {
#pragma unroll
                for (int nt = 0; nt < 2; nt++) {
                    int gc = col0 + wn * 16 + nt * 8 + (lane & 3) * 2;
                    float2 o;
                    o.x = acc[mt][nt][half * 2 + 0];
                    o.y = acc[mt][nt][half * 2 + 1];
                    *(float2*)(C + (size_t)gr * 256 + gc) = o;
                    *(__half2*)(C16 + (size_t)gr * 256 + gc) = __floats2half2_rn(o.x, o.y);
                }
            }
        }

    // ---- fused per-node dots ----
#pragma unroll
    for (int v = 0; v < 5; v++) {
        if (!vp[v]) continue;
        __syncthreads();
#pragma unroll
        for (int mt = 0; mt < 4; mt++)
#pragma unroll
            for (int half = 0; half < 2; half++) {
                float p = 0.f;
#pragma unroll
                for (int nt = 0; nt < 2; nt++) {
                    int cl = wn * 16 + nt * 8 + (lane & 3) * 2;
                    p = fmaf(acc[mt][nt][half * 2 + 0], sattn[v][cl + 0], p);
                    p = fmaf(acc[mt][nt][half * 2 + 1], sattn[v][cl + 1], p);
                }
                p += __shfl_xor_sync(0xffffffffu, p, 1);
                p += __shfl_xor_sync(0xffffffffu, p, 2);
                if ((lane & 3) == 0)
                    spart[wn][wm * 64 + mt * 16 + (lane >> 2) + half * 8] = p;
            }
        __syncthreads();
        {
            int row = tid >> 1, j = tid & 1;
            int gr = row0 + row;
            if (gr < M)
                op[v][(size_t)gr * 8 + blockIdx.y * 2 + j] =
                    spart[2 * j][row] + spart[2 * j + 1][row];
        }
    }
}

// ---------------- fused counting sort by dst (3 relations) ----------------
__global__ __launch_bounds__(256)
void count3_kernel(const int* __restrict__ e0, const int* __restrict__ e1,
                   const int* __restrict__ e2, int* __restrict__ cnt) {
    int t = blockIdx.x * 256 + threadIdx.x;
    if (t >= EED) return;
    atomicAdd(&cnt[0 * NNA + __ldg(e0 + EED + t)], 1);
    atomicAdd(&cnt[1 * NNA + __ldg(e1 + EED + t)], 1);
    atomicAdd(&cnt[2 * NNA + __ldg(e2 + EED + t)], 1);
}

// one block per relation; N = 40000, CH = 40, 1024 threads
__global__ __launch_bounds__(1024)
void scan_kernel(int* __restrict__ cnt, int* __restrict__ rowptr) {
    __shared__ int part[1024];
    const int N = NNA, CH = 40;
    int* c  = cnt + blockIdx.x * N;
    int* rp = rowptr + blockIdx.x * (N + 1);
    int t = threadIdx.x;
    int s = 0;
#pragma unroll 4
    for (int j = 0; j < CH; j++) {
        int i = t * CH + j;
        if (i < N) s += c[i];
    }
    part[t] = s;
    __syncthreads();
    for (int off = 1; off < 1024; off <<= 1) {
        int v = (t >= off) ? part[t - off] : 0;
        __syncthreads();
        part[t] += v;
        __syncthreads();
    }
    int excl = (t == 0) ? 0 : part[t - 1];
    for (int j = 0; j < CH; j++) {
        int i = t * CH + j;
        if (i < N) {
            rp[i] = excl;
            int v = c[i];
            c[i] = excl;
            excl += v;
        }
    }
    if (t == 1023) rp[N] = excl;
}

__global__ __launch_bounds__(256)
void scatter3_kernel(const int* __restrict__ e0, const int* __restrict__ e1,
                     const int* __restrict__ e2,
                     int* __restrict__ cursor, int* __restrict__ srcs) {
    int t = blockIdx.x * 256 + threadIdx.x;
    if (t >= EED) return;
    {
        int dst = __ldg(e0 + EED + t);
        int pos = atomicAdd(&cursor[0 * NNA + dst], 1);
        srcs[0 * EED + pos] = __ldg(e0 + t);
    }
    {
        int dst = __ldg(e1 + EED + t);
        int pos = atomicAdd(&cursor[1 * NNA + dst], 1);
        srcs[1 * EED + pos] = __ldg(e1 + t);
    }
    {
        int dst = __ldg(e2 + EED + t);
        int pos = atomicAdd(&cursor[2 * NNA + dst], 1);
        srcs[2 * EED + pos] = __ldg(e2 + t);
    }
}

// ---------------- CSR aggregation (fp16 gather, fused 3 relations) ----------------
__device__ __forceinline__ void accum8(float* acc, uint4 v, float ex) {
    __half2* h2 = (__half2*)&v;
#pragma unroll
    for (int j = 0; j < 4; j++) {
        float2 f = __half22float2(h2[j]);
        acc[2 * j + 0] = fmaf(ex, f.x, acc[2 * j + 0]);
        acc[2 * j + 1] = fmaf(ex, f.y, acc[2 * j + 1]);
    }
}

__global__ __launch_bounds__(256)
void agg3_kernel(const int* __restrict__ srcs_all, const int* __restrict__ rowptr_all,
                 const float* __restrict__ al1, const float* __restrict__ ar1,
                 const float* __restrict__ al2, const float* __restrict__ ar2,
                 const float* __restrict__ al0, const float* __restrict__ ar0,
                 const __half* __restrict__ hA16, const __half* __restrict__ hB16,
                 __half* __restrict__ relBA, __half* __restrict__ relAA,
                 __half* __restrict__ relAB) {
    const int rel_id = blockIdx.y;
    const int* srcs   = srcs_all + rel_id * EED;
    const int* rowptr = rowptr_all + rel_id * (NNA + 1);
    const float* al; const float* ar; const __half* hs; __half* rel;
    if (rel_id == 0)      { al = al1; ar = ar1; hs = hB16; rel = relBA; }
    else if (rel_id == 1) { al = al2; ar = ar2; hs = hA16; rel = relAA; }
    else                  { al = al0; ar = ar0; hs = hA16; rel = relAB; }

    int w    = blockIdx.x * 8 + (threadIdx.x >> 5);
    int lane = threadIdx.x & 31;
    if (w >= NNA) return;
    int head = lane >> 2;   // lane covers cols [lane*8, lane*8+8) -> head = lane>>2
    float arh = __ldg(ar + w * 8 + head);

    float acc[8];
#pragma unroll
    for (int j = 0; j < 8; j++) acc[j] = 0.f;
    float den = 0.f;

    int start = __ldg(rowptr + w);
    int end   = __ldg(rowptr + w + 1);
    for (int base = start; base < end; base += 32) {
        int n = min(32, end - base);
        int mysrc = (base + lane < end) ? __ldg(srcs + base + lane) : 0;
        int i = 0;
        for (; i + 2 <= n; i += 2) {
            int s0 = __shfl_sync(0xffffffffu, mysrc, i);
            int s1 = __shfl_sync(0xffffffffu, mysrc, i + 1);
            uint4 v0 = __ldg((const uint4*)(hs + (size_t)s0 * 256) + lane);
            uint4 v1 = __ldg((const uint4*)(hs + (size_t)s1 * 256) + lane);
            float ex0 = __expf(leaky02(__ldg(al + s0 * 8 + head) + arh));
            float ex1 = __expf(leaky02(__ldg(al + s1 * 8 + head) + arh));
            den += ex0 + ex1;
            accum8(acc, v0, ex0);
            accum8(acc, v1, ex1);
        }
        if (i < n) {
            int s0 = __shfl_sync(0xffffffffu, mysrc, i);
            uint4 v0 = __ldg((const uint4*)(hs + (size_t)s0 * 256) + lane);
            float ex0 = __expf(leaky02(__ldg(al + s0 * 8 + head) + arh));
            den += ex0;
            accum8(acc, v0, ex0);
        }
    }
    float inv = den > 0.f ? 1.f / den : 0.f;
    __half2 o[4];
#pragma unroll
    for (int j = 0; j < 4; j++)
        o[j] = __floats2half2_rn(acc[2 * j] * inv, acc[2 * j + 1] * inv);
    *((uint4*)(rel + (size_t)w * 256) + lane) = *(uint4*)o;
}

// ---------------- beta combine (rel fp16, bl precomputed) --------------
__global__ __launch_bounds__(256)
void beta_A_kernel(const float* __restrict__ h,
                   const __half* __restrict__ rel0, const __half* __restrict__ rel1,
                   const float* __restrict__ blv, const float* __restrict__ rel_r,
                   float* __restrict__ out, int N) {
    int n = blockIdx.x;
    if (n >= N) return;
    int hh   = threadIdx.x >> 5;
    int lane = threadIdx.x & 31;
    size_t idx = (size_t)n * 256 + hh * 32 + lane;

    float x  = h[idx];
    float e0 = __half2float(__ldg(rel0 + idx));
    float e1 = __half2float(__ldg(rel1 + idx));
    float rr = rel_r[hh * 32 + lane];
    float bl = blv[n * 8 + hh];
    float b0 = warp_sum(e0 * rr);
    float b1 = warp_sum(e1 * rr);
    float b2 = warp_sum(x * rr);

    float s0 = leaky02(bl + b0);
    float s1 = leaky02(bl + b1);
    float s2 = leaky02(bl + b2);
    float mx = fmaxf(s0, fmaxf(s1, s2));
    float w0 = __expf(s0 - mx), w1 = __expf(s1 - mx), w2 = __expf(s2 - mx);
    float inv = 1.f / (w0 + w1 + w2);
    float o = (e0 * w0 + e1 * w1 + x * w2) * inv;
    out[idx] = fmaxf(o, 0.f);
}

__global__ __launch_bounds__(256)
void beta_B_kernel(const float* __restrict__ h,
                   const __half* __restrict__ rel0,
                   const float* __restrict__ blv, const float* __restrict__ rel_r,
                   float* __restrict__ out, int N) {
    int n = blockIdx.x;
    if (n >= N) return;
    int hh   = threadIdx.x >> 5;
    int lane = threadIdx.x & 31;
    size_t idx = (size_t)n * 256 + hh * 32 + lane;

    float x  = h[idx];
    float e0 = __half2float(__ldg(rel0 + idx));
    float rr = rel_r[hh * 32 + lane];
    float bl = blv[n * 8 + hh];
    float b0 = warp_sum(e0 * rr);
    float b1 = warp_sum(x * rr);

    float s0 = leaky02(bl + b0);
    float s1 = leaky02(bl + b1);
    float mx = fmaxf(s0, s1);
    float w0 = __expf(s0 - mx), w1 = __expf(s1 - mx);
    float inv = 1.f / (w0 + w1);
    float o = (e0 * w0 + x * w1) * inv;
    out[idx] = fmaxf(o, 0.f);
}

// ---------------- launch ----------------
extern "C" void kernel_launch(void* const* d_in, const int* in_sizes, int n_in,
                              void* d_out, int out_size) {
    const float* x_A     = (const float*)d_in[0];
    const float* x_B     = (const float*)d_in[1];
    const int*   e_ab    = (const int*)d_in[2];
    const int*   e_ba    = (const int*)d_in[3];
    const int*   e_aa    = (const int*)d_in[4];
    const float* W_A     = (const float*)d_in[5];
    const float* b_A     = (const float*)d_in[6];
    const float* W_B     = (const float*)d_in[7];
    const float* b_B     = (const float*)d_in[8];
    const float* attn_l  = (const float*)d_in[9];   // [3,8,32]
    const float* attn_r  = (const float*)d_in[10];
    const float* rel_l_A = (const float*)d_in[11];
    const float* rel_r_A = (const float*)d_in[12];
    const float* rel_l_B = (const float*)d_in[13];
    const float* rel_r_B = (const float*)d_in[14];
    float* out = (float*)d_out;

    void *p_relBA, *p_relAA, *p_relAB, *p_hA, *p_hB, *p_hA16, *p_hB16;
    void *p_al0, *p_ar0, *p_al1, *p_ar1, *p_al2, *p_ar2, *p_blA, *p_blB;
    void *p_srcs, *p_cnt, *p_rowptr;
    cudaGetSymbolAddress(&p_relBA, g_relBA);
    cudaGetSymbolAddress(&p_relAA, g_relAA);
    cudaGetSymbolAddress(&p_relAB, g_relAB);
    cudaGetSymbolAddress(&p_hA, g_hA);
    cudaGetSymbolAddress(&p_hB, g_hB);
    cudaGetSymbolAddress(&p_hA16, g_hA16);
    cudaGetSymbolAddress(&p_hB16, g_hB16);
    cudaGetSymbolAddress(&p_al0, g_al0);
    cudaGetSymbolAddress(&p_ar0, g_ar0);
    cudaGetSymbolAddress(&p_al1, g_al1);
    cudaGetSymbolAddress(&p_ar1, g_ar1);
    cudaGetSymbolAddress(&p_al2, g_al2);
    cudaGetSymbolAddress(&p_ar2, g_ar2);
    cudaGetSymbolAddress(&p_blA, g_blA);
    cudaGetSymbolAddress(&p_blB, g_blB);
    cudaGetSymbolAddress(&p_srcs, g_srcs);
    cudaGetSymbolAddress(&p_cnt, g_cnt);
    cudaGetSymbolAddress(&p_rowptr, g_rowptr);

    float* hA   = (float*)p_hA;
    float* hB   = (float*)p_hB;
    int* cnt    = (int*)p_cnt;
    int* rowptr = (int*)p_rowptr;
    int* srcs   = (int*)p_srcs;

    cudaMemsetAsync(cnt, 0, sizeof(int) * 3 * NNA, 0);

    // 1) projections with fused per-node dots + fp16 copies
    {
        dim3 grid((NNA + 127) / 128, 4);
        gemm_fused<<<grid, 256>>>(x_A, W_A, b_A, hA, (__half*)p_hA16, NNA,
                                  attn_l + 0 * 256, attn_r + 1 * 256,
                                  attn_l + 2 * 256, attn_r + 2 * 256, rel_l_A,
                                  (float*)p_al0, (float*)p_ar1,
                                  (float*)p_al2, (float*)p_ar2, (float*)p_blA);
        gemm_fused<<<grid, 256>>>(x_B, W_B, b_B, hB, (__half*)p_hB16, NNB,
                                  attn_r + 0 * 256, attn_l + 1 * 256,
                                  (const float*)0, (const float*)0, rel_l_B,
                                  (float*)p_ar0, (float*)p_al1,
                                  (float*)0, (float*)0, (float*)p_blB);
    }

    // 2) counting sort by dst (relation order: 0=BA, 1=AA, 2=AB)
    {
        int g = (EED + 255) / 256;
        count3_kernel<<<g, 256>>>(e_ba, e_aa, e_ab, cnt);
        scan_kernel<<<3, 1024>>>(cnt, rowptr);
        scatter3_kernel<<<g, 256>>>(e_ba, e_aa, e_ab, cnt, srcs);
    }

    // 3) CSR aggregation (fp16 gather, normalized, fp16 output), 3 relations in grid.y
    {
        dim3 grid((NNA + 7) / 8, 3);
        agg3_kernel<<<grid, 256>>>(srcs, rowptr,
                                   (float*)p_al1, (float*)p_ar1,
                                   (float*)p_al2, (float*)p_ar2,
                                   (float*)p_al0, (float*)p_ar0,
                                   (const __half*)p_hA16, (const __half*)p_hB16,
                                   (__half*)p_relBA, (__half*)p_relAA, (__half*)p_relAB);
    }

    // 4) beta combine + relu -> output
    beta_A_kernel<<<NNA, 256>>>(hA, (const __half*)p_relBA, (const __half*)p_relAA,
                                (float*)p_blA, rel_r_A, out, NNA);
    beta_B_kernel<<<NNB, 256>>>(hB, (const __half*)p_relAB,
                                (float*)p_blB, rel_r_B, out + (size_t)NNA * 256, NNB);

    (void)in_sizes; (void)n_in; (void)out_size;
}

// round 5
// speedup vs baseline: 2.8703x; 1.4746x over previous
#include <cuda_runtime.h>
#include <cuda_bf16.h>
#include <cuda_fp16.h>
#include <math.h>
#include <stdint.h>

// Problem constants (fixed shapes per reference)
#define NNA 40000
#define NNB 40000
#define EED 400000
#define DD  256
#define HH  8
#define RPSTR 40004   // rowptr per-relation stride (NNA+1 padded to mult of 4)

// ---------------- scratch (static device globals; no allocation) ----------------
__device__ float  g_hA[NNA * DD];
__device__ float  g_hB[NNB * DD];
__device__ __half g_hA16[NNA * DD];
__device__ __half g_hB16[NNB * DD];
__device__ float  g_al0[NNA * HH];
__device__ float  g_ar0[NNB * HH];
__device__ float  g_al1[NNB * HH];
__device__ float  g_ar1[NNA * HH];
__device__ float  g_al2[NNA * HH];
__device__ float  g_ar2[NNA * HH];
__device__ float  g_blA[NNA * HH];
__device__ float  g_blB[NNB * HH];
__device__ int    g_srcs[3 * EED];
__device__ int    g_cnt[3 * NNA];       // counts -> scatter cursors
__device__ int    g_rowptr[3 * RPSTR];
__device__ int    g_blocksum[128];

// ---------------- helpers ----------------
__device__ __forceinline__ float leaky02(float x) { return x > 0.f ? x : 0.2f * x; }

__device__ __forceinline__ uint32_t smem_u32(const void* p) {
    uint32_t a;
    asm("{ .reg .u64 t; cvta.to.shared.u64 t, %1; cvt.u32.u64 %0, t; }" : "=r"(a) : "l"(p));
    return a;
}
__device__ __forceinline__ void ldsm4(uint32_t* r, uint32_t a) {
    asm volatile("ldmatrix.sync.aligned.m8n8.x4.shared.b16 {%0,%1,%2,%3}, [%4];"
                 : "=r"(r[0]), "=r"(r[1]), "=r"(r[2]), "=r"(r[3]) : "r"(a));
}
__device__ __forceinline__ void ldsm4t(uint32_t* r, uint32_t a) {
    asm volatile("ldmatrix.sync.aligned.m8n8.x4.trans.shared.b16 {%0,%1,%2,%3}, [%4];"
                 : "=r"(r[0]), "=r"(r[1]), "=r"(r[2]), "=r"(r[3]) : "r"(a));
}
__device__ __forceinline__ void mma16816(float* d, const uint32_t* a, uint32_t b0, uint32_t b1) {
    asm volatile("mma.sync.aligned.m16n8k16.row.col.f32.bf16.bf16.f32 "
                 "{%0,%1,%2,%3}, {%4,%5,%6,%7}, {%8,%9}, {%0,%1,%2,%3};"
                 : "+f"(d[0]), "+f"(d[1]), "+f"(d[2]), "+f"(d[3])
                 : "r"(a[0]), "r"(a[1]), "r"(a[2]), "r"(a[3]), "r"(b0), "r"(b1));
}
__device__ __forceinline__ void split_pair(float a, float b, uint32_t& hi, uint32_t& lo) {
    __nv_bfloat16 ah = __float2bfloat16(a);
    __nv_bfloat16 bh = __float2bfloat16(b);
    __nv_bfloat16 al = __float2bfloat16(a - __bfloat162float(ah));
    __nv_bfloat16 bl = __float2bfloat16(b - __bfloat162float(bh));
    __nv_bfloat162 H; H.x = ah; H.y = bh;
    __nv_bfloat162 L; L.x = al; L.y = bl;
    hi = *reinterpret_cast<uint32_t*>(&H);
    lo = *reinterpret_cast<uint32_t*>(&L);
}

// ---------------- GEMM + fused per-node dot products ------------------------------
#define ASTR 40
#define BSTR 72
__global__ __launch_bounds__(256)
void gemm_fused(const float* __restrict__ A, const float* __restrict__ W,
                const float* __restrict__ bias, float* __restrict__ C,
                __half* __restrict__ C16, int M,
                const float* __restrict__ v0, const float* __restrict__ v1,
                const float* __restrict__ v2, const float* __restrict__ v3,
                const float* __restrict__ v4,
                float* __restrict__ o0, float* __restrict__ o1,
                float* __restrict__ o2, float* __restrict__ o3,
                float* __restrict__ o4) {
    __shared__ __nv_bfloat16 sAhi[128 * ASTR];
    __shared__ __nv_bfloat16 sAlo[128 * ASTR];
    __shared__ __nv_bfloat16 sBhi[32 * BSTR];
    __shared__ __nv_bfloat16 sBlo[32 * BSTR];
    __shared__ float sattn[5][64];
    __shared__ float sbias[64];
    __shared__ float spart[4][128];

    const int tid  = threadIdx.x;
    const int lane = tid & 31;
    const int wid  = tid >> 5;
    const int wm   = wid & 1;
    const int wn   = wid >> 1;
    const int row0 = blockIdx.x * 128;
    const int col0 = blockIdx.y * 64;

    const float* vp[5] = {v0, v1, v2, v3, v4};
    float* op[5] = {o0, o1, o2, o3, o4};
    if (tid < 64) sbias[tid] = __ldg(bias + col0 + tid);
#pragma unroll
    for (int v = 0; v < 5; v++)
        if (vp[v] && tid < 64) sattn[v][tid] = __ldg(vp[v] + col0 + tid);

    float acc[4][2][4];
#pragma unroll
    for (int i = 0; i < 4; i++)
#pragma unroll
        for (int j = 0; j < 2; j++)
#pragma unroll
            for (int k = 0; k < 4; k++) acc[i][j][k] = 0.f;

    float4 av[4], bv[2];
#pragma unroll
    for (int p = 0; p < 4; p++) {
        int f = tid + 256 * p, r = f >> 3, c = (f & 7) * 4;
        int gr = row0 + r;
        av[p] = (gr < M) ? __ldg((const float4*)(A + (size_t)gr * 256 + c))
                         : make_float4(0.f, 0.f, 0.f, 0.f);
    }
#pragma unroll
    for (int p = 0; p < 2; p++) {
        int f = tid + 256 * p, r = f >> 4, c = (f & 15) * 4;
        bv[p] = __ldg((const float4*)(W + (size_t)r * 256 + col0 + c));
    }

    for (int kb = 0; kb < 8; kb++) {
#pragma unroll
        for (int p = 0; p < 4; p++) {
            int f = tid + 256 * p, r = f >> 3, c = (f & 7) * 4;
            uint32_t h01, l01, h23, l23;
            split_pair(av[p].x, av[p].y, h01, l01);
            split_pair(av[p].z, av[p].w, h23, l23);
            *(uint2*)&sAhi[r * ASTR + c] = make_uint2(h01, h23);
            *(uint2*)&sAlo[r * ASTR + c] = make_uint2(l01, l23);
        }
#pragma unroll
        for (int p = 0; p < 2; p++) {
            int f = tid + 256 * p, r = f >> 4, c = (f & 15) * 4;
            uint32_t h01, l01, h23, l23;
            split_pair(bv[p].x, bv[p].y, h01, l01);
            split_pair(bv[p].z, bv[p].w, h23, l23);
            *(uint2*)&sBhi[r * BSTR + c] = make_uint2(h01, h23);
            *(uint2*)&sBlo[r * BSTR + c] = make_uint2(l01, l23);
        }
        __syncthreads();

        if (kb < 7) {
            int k0 = (kb + 1) * 32;
#pragma unroll
            for (int p = 0; p < 4; p++) {
                int f = tid + 256 * p, r = f >> 3, c = (f & 7) * 4;
                int gr = row0 + r;
                av[p] = (gr < M) ? __ldg((const float4*)(A + (size_t)gr * 256 + k0 + c))
                                 : make_float4(0.f, 0.f, 0.f, 0.f);
            }
#pragma unroll
            for (int p = 0; p < 2; p++) {
                int f = tid + 256 * p, r = f >> 4, c = (f & 15) * 4;
                bv[p] = __ldg((const float4*)(W + (size_t)(k0 + r) * 256 + col0 + c));
            }
        }

#pragma unroll
        for (int kk = 0; kk < 32; kk += 16) {
            uint32_t ahi[4][4], alo[4][4], bh[4], bl[4];
            int arow = wm * 64 + (lane & 15);
            int acol = kk + ((lane >> 4) << 3);
#pragma unroll
            for (int mt = 0; mt < 4; mt++)
                ldsm4(ahi[mt], smem_u32(&sAhi[(arow + mt * 16) * ASTR + acol]));
            {
                int brow = kk + (lane & 7) + ((lane >> 3) & 1) * 8;
                int bcol = wn * 16 + ((lane >> 4) << 3);
                ldsm4t(bh, smem_u32(&sBhi[brow * BSTR + bcol]));
                ldsm4t(bl, smem_u32(&sBlo[brow * BSTR + bcol]));
            }
#pragma unroll
            for (int mt = 0; mt < 4; mt++)
                ldsm4(alo[mt], smem_u32(&sAlo[(arow + mt * 16) * ASTR + acol]));

#pragma unroll
            for (int mt = 0; mt < 4; mt++)
#pragma unroll
                for (int nt = 0; nt < 2; nt++) {
                    mma16816(acc[mt][nt], ahi[mt], bh[nt * 2], bh[nt * 2 + 1]);
                    mma16816(acc[mt][nt], ahi[mt], bl[nt * 2], bl[nt * 2 + 1]);
                    mma16816(acc[mt][nt], alo[mt], bh[nt * 2], bh[nt * 2 + 1]);
                }
        }
        __syncthreads();
    }

    // ---- epilogue: bias, store fp32 + fp16 copies ----
#pragma unroll
    for (int mt = 0; mt < 4; mt++)
#pragma unroll
        for (int nt = 0; nt < 2; nt++) {
            int cl = wn * 16 + nt * 8 + (lane & 3) * 2;
#pragma unroll
            for (int half = 0; half < 2; half++) {
                acc[mt][nt][half * 2 + 0] += sbias[cl + 0];
                acc[mt][nt][half * 2 + 1] += sbias[cl + 1];
            }
        }
#pragma unroll
    for (int mt = 0; mt < 4; mt++)
#pragma unroll
        for (int half = 0; half < 2; half++) {
            int gr = row0 + wm * 64 + mt * 16 + (lane >> 2) + half * 8;
            if (gr < M) {
#pragma unroll
                for (int nt = 0; nt < 2; nt++) {
                    int gc = col0 + wn * 16 + nt * 8 + (lane & 3) * 2;
                    float2 o;
                    o.x = acc[mt][nt][half * 2 + 0];
                    o.y = acc[mt][nt][half * 2 + 1];
                    *(float2*)(C + (size_t)gr * 256 + gc) = o;
                    *(__half2*)(C16 + (size_t)gr * 256 + gc) = __floats2half2_rn(o.x, o.y);
                }
            }
        }

    // ---- fused per-node dots ----
#pragma unroll
    for (int v = 0; v < 5; v++) {
        if (!vp[v]) continue;
        __syncthreads();
#pragma unroll
        for (int mt = 0; mt < 4; mt++)
#pragma unroll
            for (int half = 0; half < 2; half++) {
                float p = 0.f;
#pragma unroll
                for (int nt = 0; nt < 2; nt++) {
                    int cl = wn * 16 + nt * 8 + (lane & 3) * 2;
                    p = fmaf(acc[mt][nt][half * 2 + 0], sattn[v][cl + 0], p);
                    p = fmaf(acc[mt][nt][half * 2 + 1], sattn[v][cl + 1], p);
                }
                p += __shfl_xor_sync(0xffffffffu, p, 1);
                p += __shfl_xor_sync(0xffffffffu, p, 2);
                if ((lane & 3) == 0)
                    spart[wn][wm * 64 + mt * 16 + (lane >> 2) + half * 8] = p;
            }
        __syncthreads();
        {
            int row = tid >> 1, j = tid & 1;
            int gr = row0 + row;
            if (gr < M)
                op[v][(size_t)gr * 8 + blockIdx.y * 2 + j] =
                    spart[2 * j][row] + spart[2 * j + 1][row];
        }
    }
}

// ---------------- counting sort by dst (3 relations) ----------------
__global__ __launch_bounds__(256)
void count3_kernel(const int* __restrict__ e0, const int* __restrict__ e1,
                   const int* __restrict__ e2, int* __restrict__ cnt) {
    int t = blockIdx.x * 256 + threadIdx.x;
    if (t >= EED) return;
    atomicAdd(&cnt[0 * NNA + __ldg(e0 + EED + t)], 1);
    atomicAdd(&cnt[1 * NNA + __ldg(e1 + EED + t)], 1);
    atomicAdd(&cnt[2 * NNA + __ldg(e2 + EED + t)], 1);
}

// hierarchical scan: 120 blocks x 1000 elems
__global__ __launch_bounds__(256)
void scan_blocks(const int* __restrict__ cnt, int* __restrict__ rowptr,
                 int* __restrict__ blocksum) {
    int bx = blockIdx.x;           // 0..119
    int r = bx / 40, ch = bx % 40;
    const int4* c4 = (const int4*)(cnt + r * NNA + ch * 1000);
    int4* rp4 = (int4*)(rowptr + r * RPSTR + ch * 1000);
    int t = threadIdx.x, lane = t & 31, wid = t >> 5;

    int4 v = make_int4(0, 0, 0, 0);
    if (t < 250) v = c4[t];
    int ts = v.x + v.y + v.z + v.w;

    int inc = ts;
#pragma unroll
    for (int off = 1; off < 32; off <<= 1) {
        int u = __shfl_up_sync(0xffffffffu, inc, off);
        if (lane >= off) inc += u;
    }
    __shared__ int wsum[8];
    if (lane == 31) wsum[wid] = inc;
    __syncthreads();
    if (wid == 0) {
        int x = (lane < 8) ? wsum[lane] : 0;
#pragma unroll
        for (int off = 1; off < 8; off <<= 1) {
            int u = __shfl_up_sync(0xffffffffu, x, off);
            if (lane >= off) x += u;
        }
        if (lane < 8) wsum[lane] = x;
    }
    __syncthreads();
    int excl = ((wid == 0) ? 0 : wsum[wid - 1]) + inc - ts;
    if (t < 250) {
        int4 o;
        o.x = excl;
        o.y = excl + v.x;
        o.z = o.y + v.y;
        o.w = o.z + v.z;
        rp4[t] = o;
    }
    if (t == 0) blocksum[bx] = wsum[7];
}

// top-level: segmented exclusive scan of 3x40 block sums (1 block, 96 threads)
__global__ __launch_bounds__(96)
void scan_top(int* __restrict__ blocksum, int* __restrict__ rowptr) {
    int r = threadIdx.x >> 5;
    int lane = threadIdx.x & 31;
    int* bs = blocksum + r * 40;
    int a = __ldg(bs + lane);
    int b = (lane < 8) ? __ldg(bs + 32 + lane) : 0;
    int ia = a, ib = b;
#pragma unroll
    for (int off = 1; off < 32; off <<= 1) {
        int u = __shfl_up_sync(0xffffffffu, ia, off);
        if (lane >= off) ia += u;
    }
#pragma unroll
    for (int off = 1; off < 8; off <<= 1) {
        int u = __shfl_up_sync(0xffffffffu, ib, off);
        if (lane >= off) ib += u;
    }
    int tot32 = __shfl_sync(0xffffffffu, ia, 31);
    int totb  = __shfl_sync(0xffffffffu, ib, 7);
    bs[lane] = ia - a;
    if (lane < 8) bs[32 + lane] = tot32 + ib - b;
    if (lane == 0) rowptr[r * RPSTR + NNA] = tot32 + totb;
}

// add block offsets; also init scatter cursors (reuse cnt)
__global__ __launch_bounds__(256)
void scan_add(int* __restrict__ rowptr, const int* __restrict__ blocksum,
              int* __restrict__ cnt) {
    int bx = blockIdx.x;
    int r = bx / 40, ch = bx % 40;
    int t = threadIdx.x;
    if (t >= 250) return;
    int off = __ldg(blocksum + bx);
    int4* rp4 = (int4*)(rowptr + r * RPSTR + ch * 1000);
    int4* cu4 = (int4*)(cnt + r * NNA + ch * 1000);
    int4 v = rp4[t];
    v.x += off; v.y += off; v.z += off; v.w += off;
    rp4[t] = v;
    cu4[t] = v;
}

__global__ __launch_bounds__(256)
void scatter3_kernel(const int* __restrict__ e0, const int* __restrict__ e1,
                     const int* __restrict__ e2,
                     int* __restrict__ cursor, int* __restrict__ srcs) {
    int t = blockIdx.x * 256 + threadIdx.x;
    if (t >= EED) return;
    {
        int dst = __ldg(e0 + EED + t);
        int pos = atomicAdd(&cursor[0 * NNA + dst], 1);
        srcs[0 * EED + pos] = __ldg(e0 + t);
    }
    {
        int dst = __ldg(e1 + EED + t);
        int pos = atomicAdd(&cursor[1 * NNA + dst], 1);
        srcs[1 * EED + pos] = __ldg(e1 + t);
    }
    {
        int dst = __ldg(e2 + EED + t);
        int pos = atomicAdd(&cursor[2 * NNA + dst], 1);
        srcs[2 * EED + pos] = __ldg(e2 + t);
    }
}

// ---------------- fused CSR aggregation + beta combine ----------------
__device__ __forceinline__ void accum8(float* acc, uint4 v, float ex) {
    __half2* h2 = (__half2*)&v;
#pragma unroll
    for (int j = 0; j < 4; j++) {
        float2 f = __half22float2(h2[j]);
        acc[2 * j + 0] = fmaf(ex, f.x, acc[2 * j + 0]);
        acc[2 * j + 1] = fmaf(ex, f.y, acc[2 * j + 1]);
    }
}

__device__ __forceinline__ void csr_walk(const int* __restrict__ srcs,
                                         int start, int end,
                                         const float* __restrict__ al,
                                         int head, float arh,
                                         const __half* __restrict__ hs,
                                         int lane, float* acc, float& den) {
    for (int base = start; base < end; base += 32) {
        int n = min(32, end - base);
        int mysrc = (base + lane < end) ? __ldg(srcs + base + lane) : 0;
        int i = 0;
        for (; i + 2 <= n; i += 2) {
            int s0 = __shfl_sync(0xffffffffu, mysrc, i);
            int s1 = __shfl_sync(0xffffffffu, mysrc, i + 1);
            uint4 v0 = __ldg((const uint4*)(hs + (size_t)s0 * 256) + lane);
            uint4 v1 = __ldg((const uint4*)(hs + (size_t)s1 * 256) + lane);
            float ex0 = __expf(leaky02(__ldg(al + s0 * 8 + head) + arh));
            float ex1 = __expf(leaky02(__ldg(al + s1 * 8 + head) + arh));
            den += ex0 + ex1;
            accum8(acc, v0, ex0);
            accum8(acc, v1, ex1);
        }
        if (i < n) {
            int s0 = __shfl_sync(0xffffffffu, mysrc, i);
            uint4 v0 = __ldg((const uint4*)(hs + (size_t)s0 * 256) + lane);
            float ex0 = __expf(leaky02(__ldg(al + s0 * 8 + head) + arh));
            den += ex0;
            accum8(acc, v0, ex0);
        }
    }
}

__device__ __forceinline__ float quad_sum(float p) {
    p += __shfl_xor_sync(0xffffffffu, p, 1);
    p += __shfl_xor_sync(0xffffffffu, p, 2);
    return p;
}

// A side: relations 0 (B->A) and 1 (A->A), R=3 with self
__global__ __launch_bounds__(256)
void aggbeta_A(const int* __restrict__ srcs_all, const int* __restrict__ rowptr,
               const float* __restrict__ al1, const float* __restrict__ ar1,
               const float* __restrict__ al2, const float* __restrict__ ar2,
               const __half* __restrict__ hB16, const __half* __restrict__ hA16,
               const float* __restrict__ hA,
               const float* __restrict__ blA, const float* __restrict__ rel_r,
               float* __restrict__ out) {
    int w = blockIdx.x * 8 + (threadIdx.x >> 5);
    int lane = threadIdx.x & 31;
    if (w >= NNA) return;
    int head = lane >> 2;

    float acc0[8], acc1[8];
#pragma unroll
    for (int j = 0; j < 8; j++) { acc0[j] = 0.f; acc1[j] = 0.f; }
    float den0 = 0.f, den1 = 0.f;

    {
        int s = __ldg(rowptr + 0 * RPSTR + w), e = __ldg(rowptr + 0 * RPSTR + w + 1);
        csr_walk(srcs_all + 0 * EED, s, e, al1, head,
                 __ldg(ar1 + w * 8 + head), hB16, lane, acc0, den0);
    }
    {
        int s = __ldg(rowptr + 1 * RPSTR + w), e = __ldg(rowptr + 1 * RPSTR + w + 1);
        csr_walk(srcs_all + 1 * EED, s, e, al2, head,
                 __ldg(ar2 + w * 8 + head), hA16, lane, acc1, den1);
    }
    float inv0 = den0 > 0.f ? 1.f / den0 : 0.f;
    float inv1 = den1 > 0.f ? 1.f / den1 : 0.f;
#pragma unroll
    for (int j = 0; j < 8; j++) { acc0[j] *= inv0; acc1[j] *= inv1; }

    float4 x0 = __ldg((const float4*)(hA + (size_t)w * 256) + lane * 2);
    float4 x1 = __ldg((const float4*)(hA + (size_t)w * 256) + lane * 2 + 1);
    float4 r0 = __ldg((const float4*)rel_r + lane * 2);
    float4 r1 = __ldg((const float4*)rel_r + lane * 2 + 1);
    float xs[8] = {x0.x, x0.y, x0.z, x0.w, x1.x, x1.y, x1.z, x1.w};
    float rs[8] = {r0.x, r0.y, r0.z, r0.w, r1.x, r1.y, r1.z, r1.w};

    float p0 = 0.f, p1 = 0.f, p2 = 0.f;
#pragma unroll
    for (int j = 0; j < 8; j++) {
        p0 = fmaf(acc0[j], rs[j], p0);
        p1 = fmaf(acc1[j], rs[j], p1);
        p2 = fmaf(xs[j],   rs[j], p2);
    }
    float b0 = quad_sum(p0), b1 = quad_sum(p1), b2 = quad_sum(p2);
    float bl = __ldg(blA + w * 8 + head);

    float s0 = leaky02(bl + b0);
    float s1 = leaky02(bl + b1);
    float s2 = leaky02(bl + b2);
    float mx = fmaxf(s0, fmaxf(s1, s2));
    float w0 = __expf(s0 - mx), w1 = __expf(s1 - mx), w2 = __expf(s2 - mx);
    float inv = 1.f / (w0 + w1 + w2);

    float o[8];
#pragma unroll
    for (int j = 0; j < 8; j++)
        o[j] = fmaxf((acc0[j] * w0 + acc1[j] * w1 + xs[j] * w2) * inv, 0.f);
    float4* op = (float4*)(out + (size_t)w * 256);
    op[lane * 2]     = make_float4(o[0], o[1], o[2], o[3]);
    op[lane * 2 + 1] = make_float4(o[4], o[5], o[6], o[7]);
}

// B side: relation 2 (A->B), R=2 with self
__global__ __launch_bounds__(256)
void aggbeta_B(const int* __restrict__ srcs_all, const int* __restrict__ rowptr,
               const float* __restrict__ al0, const float* __restrict__ ar0,
               const __half* __restrict__ hA16, const float* __restrict__ hB,
               const float* __restrict__ blB, const float* __restrict__ rel_r,
               float* __restrict__ out) {
    int w = blockIdx.x * 8 + (threadIdx.x >> 5);
    int lane = threadIdx.x & 31;
    if (w >= NNB) return;
    int head = lane >> 2;

    float acc0[8];
#pragma unroll
    for (int j = 0; j < 8; j++) acc0[j] = 0.f;
    float den0 = 0.f;
    {
        int s = __ldg(rowptr + 2 * RPSTR + w), e = __ldg(rowptr + 2 * RPSTR + w + 1);
        csr_walk(srcs_all + 2 * EED, s, e, al0, head,
                 __ldg(ar0 + w * 8 + head), hA16, lane, acc0, den0);
    }
    float inv0 = den0 > 0.f ? 1.f / den0 : 0.f;
#pragma unroll
    for (int j = 0; j < 8; j++) acc0[j] *= inv0;

    float4 x0 = __ldg((const float4*)(hB + (size_t)w * 256) + lane * 2);
    float4 x1 = __ldg((const float4*)(hB + (size_t)w * 256) + lane * 2 + 1);
    float4 r0 = __ldg((const float4*)rel_r + lane * 2);
    float4 r1 = __ldg((const float4*)rel_r + lane * 2 + 1);
    float xs[8] = {x0.x, x0.y, x0.z, x0.w, x1.x, x1.y, x1.z, x1.w};
    float rs[8] = {r0.x, r0.y, r0.z, r0.w, r1.x, r1.y, r1.z, r1.w};

    float p0 = 0.f, p1 = 0.f;
#pragma unroll
    for (int j = 0; j < 8; j++) {
        p0 = fmaf(acc0[j], rs[j], p0);
        p1 = fmaf(xs[j],   rs[j], p1);
    }
    float b0 = quad_sum(p0), b1 = quad_sum(p1);
    float bl = __ldg(blB + w * 8 + head);

    float s0 = leaky02(bl + b0);
    float s1 = leaky02(bl + b1);
    float mx = fmaxf(s0, s1);
    float w0 = __expf(s0 - mx), w1 = __expf(s1 - mx);
    float inv = 1.f / (w0 + w1);

    float o[8];
#pragma unroll
    for (int j = 0; j < 8; j++)
        o[j] = fmaxf((acc0[j] * w0 + xs[j] * w1) * inv, 0.f);
    float4* op = (float4*)(out + (size_t)w * 256);
    op[lane * 2]     = make_float4(o[0], o[1], o[2], o[3]);
    op[lane * 2 + 1] = make_float4(o[4], o[5], o[6], o[7]);
}

// ---------------- launch ----------------
extern "C" void kernel_launch(void* const* d_in, const int* in_sizes, int n_in,
                              void* d_out, int out_size) {
    const float* x_A     = (const float*)d_in[0];
    const float* x_B     = (const float*)d_in[1];
    const int*   e_ab    = (const int*)d_in[2];
    const int*   e_ba    = (const int*)d_in[3];
    const int*   e_aa    = (const int*)d_in[4];
    const float* W_A     = (const float*)d_in[5];
    const float* b_A     = (const float*)d_in[6];
    const float* W_B     = (const float*)d_in[7];
    const float* b_B     = (const float*)d_in[8];
    const float* attn_l  = (const float*)d_in[9];   // [3,8,32]
    const float* attn_r  = (const float*)d_in[10];
    const float* rel_l_A = (const float*)d_in[11];
    const float* rel_r_A = (const float*)d_in[12];
    const float* rel_l_B = (const float*)d_in[13];
    const float* rel_r_B = (const float*)d_in[14];
    float* out = (float*)d_out;

    void *p_hA, *p_hB, *p_hA16, *p_hB16;
    void *p_al0, *p_ar0, *p_al1, *p_ar1, *p_al2, *p_ar2, *p_blA, *p_blB;
    void *p_srcs, *p_cnt, *p_rowptr, *p_bsum;
    cudaGetSymbolAddress(&p_hA, g_hA);
    cudaGetSymbolAddress(&p_hB, g_hB);
    cudaGetSymbolAddress(&p_hA16, g_hA16);
    cudaGetSymbolAddress(&p_hB16, g_hB16);
    cudaGetSymbolAddress(&p_al0, g_al0);
    cudaGetSymbolAddress(&p_ar0, g_ar0);
    cudaGetSymbolAddress(&p_al1, g_al1);
    cudaGetSymbolAddress(&p_ar1, g_ar1);
    cudaGetSymbolAddress(&p_al2, g_al2);
    cudaGetSymbolAddress(&p_ar2, g_ar2);
    cudaGetSymbolAddress(&p_blA, g_blA);
    cudaGetSymbolAddress(&p_blB, g_blB);
    cudaGetSymbolAddress(&p_srcs, g_srcs);
    cudaGetSymbolAddress(&p_cnt, g_cnt);
    cudaGetSymbolAddress(&p_rowptr, g_rowptr);
    cudaGetSymbolAddress(&p_bsum, g_blocksum);

    float* hA   = (float*)p_hA;
    float* hB   = (float*)p_hB;
    int* cnt    = (int*)p_cnt;
    int* rowptr = (int*)p_rowptr;
    int* srcs   = (int*)p_srcs;
    int* bsum   = (int*)p_bsum;

    cudaMemsetAsync(cnt, 0, sizeof(int) * 3 * NNA, 0);

    // counting sort (independent of GEMM): count -> hierarchical scan -> scatter
    {
        int g = (EED + 255) / 256;
        count3_kernel<<<g, 256>>>(e_ba, e_aa, e_ab, cnt);
        scan_blocks<<<120, 256>>>(cnt, rowptr, bsum);
        scan_top<<<1, 96>>>(bsum, rowptr);
        scan_add<<<120, 256>>>(rowptr, bsum, cnt);
        scatter3_kernel<<<g, 256>>>(e_ba, e_aa, e_ab, cnt, srcs);
    }

    // projections with fused per-node dots + fp16 copies
    {
        dim3 grid((NNA + 127) / 128, 4);
        gemm_fused<<<grid, 256>>>(x_A, W_A, b_A, hA, (__half*)p_hA16, NNA,
                                  attn_l + 0 * 256, attn_r + 1 * 256,
                                  attn_l + 2 * 256, attn_r + 2 * 256, rel_l_A,
                                  (float*)p_al0, (float*)p_ar1,
                                  (float*)p_al2, (float*)p_ar2, (float*)p_blA);
        gemm_fused<<<grid, 256>>>(x_B, W_B, b_B, hB, (__half*)p_hB16, NNB,
                                  attn_r + 0 * 256, attn_l + 1 * 256,
                                  (const float*)0, (const float*)0, rel_l_B,
                                  (float*)p_ar0, (float*)p_al1,
                                  (float*)0, (float*)0, (float*)p_blB);
    }

    // fused aggregation + beta + relu -> output
    aggbeta_A<<<(NNA + 7) / 8, 256>>>(srcs, rowptr,
                                      (float*)p_al1, (float*)p_ar1,
                                      (float*)p_al2, (float*)p_ar2,
                                      (const __half*)p_hB16, (const __half*)p_hA16,
                                      hA, (float*)p_blA, rel_r_A, out);
    aggbeta_B<<<(NNB + 7) / 8, 256>>>(srcs, rowptr,
                                      (float*)p_al0, (float*)p_ar0,
                                      (const __half*)p_hA16,
                                      hB, (float*)p_blB, rel_r_B,
                                      out + (size_t)NNA * 256);

    (void)in_sizes; (void)n_in; (void)out_size;
}

// round 6
// speedup vs baseline: 3.1436x; 1.0952x over previous
#include <cuda_runtime.h>
#include <cuda_bf16.h>
#include <cuda_fp16.h>
#include <math.h>
#include <stdint.h>

// Problem constants (fixed shapes per reference)
#define NNA 40000
#define NNB 40000
#define EED 400000
#define DD  256
#define HH  8
#define RPSTR 40004   // rowptr per-relation stride

// ---------------- scratch (static device globals; no allocation) ----------------
__device__ __half g_hA16[NNA * DD];
__device__ __half g_hB16[NNB * DD];
__device__ float  g_al0[NNA * HH];
__device__ float  g_ar0[NNB * HH];
__device__ float  g_al1[NNB * HH];
__device__ float  g_ar1[NNA * HH];
__device__ float  g_al2[NNA * HH];
__device__ float  g_ar2[NNA * HH];
__device__ float  g_blA[NNA * HH];
__device__ float  g_blB[NNB * HH];
__device__ int    g_srcs[3 * EED];
__device__ int    g_cnt[3 * NNA];
__device__ int    g_rowptr[3 * RPSTR];
__device__ int    g_blocksum[128];

// ---------------- helpers ----------------
__device__ __forceinline__ float leaky02(float x) { return x > 0.f ? x : 0.2f * x; }

__device__ __forceinline__ uint32_t smem_u32(const void* p) {
    uint32_t a;
    asm("{ .reg .u64 t; cvta.to.shared.u64 t, %1; cvt.u32.u64 %0, t; }" : "=r"(a) : "l"(p));
    return a;
}
__device__ __forceinline__ void ldsm4(uint32_t* r, uint32_t a) {
    asm volatile("ldmatrix.sync.aligned.m8n8.x4.shared.b16 {%0,%1,%2,%3}, [%4];"
                 : "=r"(r[0]), "=r"(r[1]), "=r"(r[2]), "=r"(r[3]) : "r"(a));
}
__device__ __forceinline__ void ldsm4t(uint32_t* r, uint32_t a) {
    asm volatile("ldmatrix.sync.aligned.m8n8.x4.trans.shared.b16 {%0,%1,%2,%3}, [%4];"
                 : "=r"(r[0]), "=r"(r[1]), "=r"(r[2]), "=r"(r[3]) : "r"(a));
}
__device__ __forceinline__ void mma16816(float* d, const uint32_t* a, uint32_t b0, uint32_t b1) {
    asm volatile("mma.sync.aligned.m16n8k16.row.col.f32.bf16.bf16.f32 "
                 "{%0,%1,%2,%3}, {%4,%5,%6,%7}, {%8,%9}, {%0,%1,%2,%3};"
                 : "+f"(d[0]), "+f"(d[1]), "+f"(d[2]), "+f"(d[3])
                 : "r"(a[0]), "r"(a[1]), "r"(a[2]), "r"(a[3]), "r"(b0), "r"(b1));
}
__device__ __forceinline__ void split_pair(float a, float b, uint32_t& hi, uint32_t& lo) {
    __nv_bfloat16 ah = __float2bfloat16(a);
    __nv_bfloat16 bh = __float2bfloat16(b);
    __nv_bfloat16 al = __float2bfloat16(a - __bfloat162float(ah));
    __nv_bfloat16 bl = __float2bfloat16(b - __bfloat162float(bh));
    __nv_bfloat162 H; H.x = ah; H.y = bh;
    __nv_bfloat162 L; L.x = al; L.y = bl;
    hi = *reinterpret_cast<uint32_t*>(&H);
    lo = *reinterpret_cast<uint32_t*>(&L);
}

// ---------------- merged GEMM (A and B sides via blockIdx.z) -----------------------
// h16 = fp16(x @ W + bias); fused per-node dots o[n,h] = sum_c h[n,h,c]*v[h,c]
#define ASTR 40
#define BSTR 72
__global__ __launch_bounds__(256)
void gemm_fused2(const float* __restrict__ xA, const float* __restrict__ xB,
                 const float* __restrict__ WA, const float* __restrict__ WB,
                 const float* __restrict__ bA_, const float* __restrict__ bB_,
                 __half* __restrict__ hA16, __half* __restrict__ hB16,
                 const float* __restrict__ attn_l, const float* __restrict__ attn_r,
                 const float* __restrict__ rel_l_A, const float* __restrict__ rel_l_B,
                 float* __restrict__ al0, float* __restrict__ ar1,
                 float* __restrict__ al2, float* __restrict__ ar2,
                 float* __restrict__ blA,
                 float* __restrict__ ar0, float* __restrict__ al1,
                 float* __restrict__ blB) {
    __shared__ __nv_bfloat16 sAhi[128 * ASTR];
    __shared__ __nv_bfloat16 sAlo[128 * ASTR];
    __shared__ __nv_bfloat16 sBhi[32 * BSTR];
    __shared__ __nv_bfloat16 sBlo[32 * BSTR];
    __shared__ float sattn[5][64];
    __shared__ float sbias[64];
    __shared__ float spart[4][128];

    const int tid  = threadIdx.x;
    const int lane = tid & 31;
    const int wid  = tid >> 5;
    const int wm   = wid & 1;
    const int wn   = wid >> 1;
    const int row0 = blockIdx.x * 128;
    const int col0 = blockIdx.y * 64;
    const int M = NNA;

    const float* A; const float* W; const float* bias; __half* C16;
    const float* vp[5]; float* op[5];
    if (blockIdx.z == 0) {
        A = xA; W = WA; bias = bA_; C16 = hA16;
        vp[0] = attn_l + 0;   op[0] = al0;
        vp[1] = attn_r + 256; op[1] = ar1;
        vp[2] = attn_l + 512; op[2] = al2;
        vp[3] = attn_r + 512; op[3] = ar2;
        vp[4] = rel_l_A;      op[4] = blA;
    } else {
        A = xB; W = WB; bias = bB_; C16 = hB16;
        vp[0] = attn_r + 0;   op[0] = ar0;
        vp[1] = attn_l + 256; op[1] = al1;
        vp[2] = 0;            op[2] = 0;
        vp[3] = 0;            op[3] = 0;
        vp[4] = rel_l_B;      op[4] = blB;
    }

    if (tid < 64) sbias[tid] = __ldg(bias + col0 + tid);
#pragma unroll
    for (int v = 0; v < 5; v++)
        if (vp[v] && tid < 64) sattn[v][tid] = __ldg(vp[v] + col0 + tid);

    float acc[4][2][4];
#pragma unroll
    for (int i = 0; i < 4; i++)
#pragma unroll
        for (int j = 0; j < 2; j++)
#pragma unroll
            for (int k = 0; k < 4; k++) acc[i][j][k] = 0.f;

    float4 av[4], bv[2];
#pragma unroll
    for (int p = 0; p < 4; p++) {
        int f = tid + 256 * p, r = f >> 3, c = (f & 7) * 4;
        int gr = row0 + r;
        av[p] = (gr < M) ? __ldg((const float4*)(A + (size_t)gr * 256 + c))
                         : make_float4(0.f, 0.f, 0.f, 0.f);
    }
#pragma unroll
    for (int p = 0; p < 2; p++) {
        int f = tid + 256 * p, r = f >> 4, c = (f & 15) * 4;
        bv[p] = __ldg((const float4*)(W + (size_t)r * 256 + col0 + c));
    }

    for (int kb = 0; kb < 8; kb++) {
#pragma unroll
        for (int p = 0; p < 4; p++) {
            int f = tid + 256 * p, r = f >> 3, c = (f & 7) * 4;
            uint32_t h01, l01, h23, l23;
            split_pair(av[p].x, av[p].y, h01, l01);
            split_pair(av[p].z, av[p].w, h23, l23);
            *(uint2*)&sAhi[r * ASTR + c] = make_uint2(h01, h23);
            *(uint2*)&sAlo[r * ASTR + c] = make_uint2(l01, l23);
        }
#pragma unroll
        for (int p = 0; p < 2; p++) {
            int f = tid + 256 * p, r = f >> 4, c = (f & 15) * 4;
            uint32_t h01, l01, h23, l23;
            split_pair(bv[p].x, bv[p].y, h01, l01);
            split_pair(bv[p].z, bv[p].w, h23, l23);
            *(uint2*)&sBhi[r * BSTR + c] = make_uint2(h01, h23);
            *(uint2*)&sBlo[r * BSTR + c] = make_uint2(l01, l23);
        }
        __syncthreads();

        if (kb < 7) {
            int k0 = (kb + 1) * 32;
#pragma unroll
            for (int p = 0; p < 4; p++) {
                int f = tid + 256 * p, r = f >> 3, c = (f & 7) * 4;
                int gr = row0 + r;
                av[p] = (gr < M) ? __ldg((const float4*)(A + (size_t)gr * 256 + k0 + c))
                                 : make_float4(0.f, 0.f, 0.f, 0.f);
            }
#pragma unroll
            for (int p = 0; p < 2; p++) {
                int f = tid + 256 * p, r = f >> 4, c = (f & 15) * 4;
                bv[p] = __ldg((const float4*)(W + (size_t)(k0 + r) * 256 + col0 + c));
            }
        }

#pragma unroll
        for (int kk = 0; kk < 32; kk += 16) {
            uint32_t ahi[4][4], alo[4][4], bh[4], bl[4];
            int arow = wm * 64 + (lane & 15);
            int acol = kk + ((lane >> 4) << 3);
#pragma unroll
            for (int mt = 0; mt < 4; mt++)
                ldsm4(ahi[mt], smem_u32(&sAhi[(arow + mt * 16) * ASTR + acol]));
            {
                int brow = kk + (lane & 7) + ((lane >> 3) & 1) * 8;
                int bcol = wn * 16 + ((lane >> 4) << 3);
                ldsm4t(bh, smem_u32(&sBhi[brow * BSTR + bcol]));
                ldsm4t(bl, smem_u32(&sBlo[brow * BSTR + bcol]));
            }
#pragma unroll
            for (int mt = 0; mt < 4; mt++)
                ldsm4(alo[mt], smem_u32(&sAlo[(arow + mt * 16) * ASTR + acol]));

#pragma unroll
            for (int mt = 0; mt < 4; mt++)
#pragma unroll
                for (int nt = 0; nt < 2; nt++) {
                    mma16816(acc[mt][nt], ahi[mt], bh[nt * 2], bh[nt * 2 + 1]);
                    mma16816(acc[mt][nt], ahi[mt], bl[nt * 2], bl[nt * 2 + 1]);
                    mma16816(acc[mt][nt], alo[mt], bh[nt * 2], bh[nt * 2 + 1]);
                }
        }
        __syncthreads();
    }

    // ---- epilogue: bias, store fp16 ----
#pragma unroll
    for (int mt = 0; mt < 4; mt++)
#pragma unroll
        for (int nt = 0; nt < 2; nt++) {
            int cl = wn * 16 + nt * 8 + (lane & 3) * 2;
#pragma unroll
            for (int half = 0; half < 2; half++) {
                acc[mt][nt][half * 2 + 0] += sbias[cl + 0];
                acc[mt][nt][half * 2 + 1] += sbias[cl + 1];
            }
        }
#pragma unroll
    for (int mt = 0; mt < 4; mt++)
#pragma unroll
        for (int half = 0; half < 2; half++) {
            int gr = row0 + wm * 64 + mt * 16 + (lane >> 2) + half * 8;
            if (gr < M) {
#pragma unroll
                for (int nt = 0; nt < 2; nt++) {
                    int gc = col0 + wn * 16 + nt * 8 + (lane & 3) * 2;
                    *(__half2*)(C16 + (size_t)gr * 256 + gc) =
                        __floats2half2_rn(acc[mt][nt][half * 2 + 0],
                                          acc[mt][nt][half * 2 + 1]);
                }
            }
        }

    // ---- fused per-node dots ----
#pragma unroll
    for (int v = 0; v < 5; v++) {
        if (!vp[v]) continue;
        __syncthreads();
#pragma unroll
        for (int mt = 0; mt < 4; mt++)
#pragma unroll
            for (int half = 0; half < 2; half++) {
                float p = 0.f;
#pragma unroll
                for (int nt = 0; nt < 2; nt++) {
                    int cl = wn * 16 + nt * 8 + (lane & 3) * 2;
                    p = fmaf(acc[mt][nt][half * 2 + 0], sattn[v][cl + 0], p);
                    p = fmaf(acc[mt][nt][half * 2 + 1], sattn[v][cl + 1], p);
                }
                p += __shfl_xor_sync(0xffffffffu, p, 1);
                p += __shfl_xor_sync(0xffffffffu, p, 2);
                if ((lane & 3) == 0)
                    spart[wn][wm * 64 + mt * 16 + (lane >> 2) + half * 8] = p;
            }
        __syncthreads();
        {
            int row = tid >> 1, j = tid & 1;
            int gr = row0 + row;
            if (gr < M)
                op[v][(size_t)gr * 8 + blockIdx.y * 2 + j] =
                    spart[2 * j][row] + spart[2 * j + 1][row];
        }
    }
}

// ---------------- counting sort by dst (3 relations) ----------------
__global__ __launch_bounds__(256)
void count3_kernel(const int* __restrict__ e0, const int* __restrict__ e1,
                   const int* __restrict__ e2, int* __restrict__ cnt) {
    int t = blockIdx.x * 256 + threadIdx.x;
    if (t >= EED) return;
    atomicAdd(&cnt[0 * NNA + __ldg(e0 + EED + t)], 1);
    atomicAdd(&cnt[1 * NNA + __ldg(e1 + EED + t)], 1);
    atomicAdd(&cnt[2 * NNA + __ldg(e2 + EED + t)], 1);
}

__global__ __launch_bounds__(256)
void scan_blocks(const int* __restrict__ cnt, int* __restrict__ rowptr,
                 int* __restrict__ blocksum) {
    int bx = blockIdx.x;           // 0..119
    int r = bx / 40, ch = bx % 40;
    const int4* c4 = (const int4*)(cnt + r * NNA + ch * 1000);
    int4* rp4 = (int4*)(rowptr + r * RPSTR + ch * 1000);
    int t = threadIdx.x, lane = t & 31, wid = t >> 5;

    int4 v = make_int4(0, 0, 0, 0);
    if (t < 250) v = c4[t];
    int ts = v.x + v.y + v.z + v.w;

    int inc = ts;
#pragma unroll
    for (int off = 1; off < 32; off <<= 1) {
        int u = __shfl_up_sync(0xffffffffu, inc, off);
        if (lane >= off) inc += u;
    }
    __shared__ int wsum[8];
    if (lane == 31) wsum[wid] = inc;
    __syncthreads();
    if (wid == 0) {
        int x = (lane < 8) ? wsum[lane] : 0;
#pragma unroll
        for (int off = 1; off < 8; off <<= 1) {
            int u = __shfl_up_sync(0xffffffffu, x, off);
            if (lane >= off) x += u;
        }
        if (lane < 8) wsum[lane] = x;
    }
    __syncthreads();
    int excl = ((wid == 0) ? 0 : wsum[wid - 1]) + inc - ts;
    if (t < 250) {
        int4 o;
        o.x = excl;
        o.y = excl + v.x;
        o.z = o.y + v.y;
        o.w = o.z + v.z;
        rp4[t] = o;
    }
    if (t == 0) blocksum[bx] = wsum[7];
}

__global__ __launch_bounds__(96)
void scan_top(int* __restrict__ blocksum, int* __restrict__ rowptr) {
    int r = threadIdx.x >> 5;
    int lane = threadIdx.x & 31;
    int* bs = blocksum + r * 40;
    int a = __ldg(bs + lane);
    int b = (lane < 8) ? __ldg(bs + 32 + lane) : 0;
    int ia = a, ib = b;
#pragma unroll
    for (int off = 1; off < 32; off <<= 1) {
        int u = __shfl_up_sync(0xffffffffu, ia, off);
        if (lane >= off) ia += u;
    }
#pragma unroll
    for (int off = 1; off < 8; off <<= 1) {
        int u = __shfl_up_sync(0xffffffffu, ib, off);
        if (lane >= off) ib += u;
    }
    int tot32 = __shfl_sync(0xffffffffu, ia, 31);
    int totb  = __shfl_sync(0xffffffffu, ib, 7);
    bs[lane] = ia - a;
    if (lane < 8) bs[32 + lane] = tot32 + ib - b;
    if (lane == 0) rowptr[r * RPSTR + NNA] = tot32 + totb;
}

__global__ __launch_bounds__(256)
void scan_add(int* __restrict__ rowptr, const int* __restrict__ blocksum,
              int* __restrict__ cnt) {
    int bx = blockIdx.x;
    int r = bx / 40, ch = bx % 40;
    int t = threadIdx.x;
    if (t >= 250) return;
    int off = __ldg(blocksum + bx);
    int4* rp4 = (int4*)(rowptr + r * RPSTR + ch * 1000);
    int4* cu4 = (int4*)(cnt + r * NNA + ch * 1000);
    int4 v = rp4[t];
    v.x += off; v.y += off; v.z += off; v.w += off;
    rp4[t] = v;
    cu4[t] = v;
}

__global__ __launch_bounds__(256)
void scatter3_kernel(const int* __restrict__ e0, const int* __restrict__ e1,
                     const int* __restrict__ e2,
                     int* __restrict__ cursor, int* __restrict__ srcs) {
    int t = blockIdx.x * 256 + threadIdx.x;
    if (t >= EED) return;
    {
        int dst = __ldg(e0 + EED + t);
        int pos = atomicAdd(&cursor[0 * NNA + dst], 1);
        srcs[0 * EED + pos] = __ldg(e0 + t);
    }
    {
        int dst = __ldg(e1 + EED + t);
        int pos = atomicAdd(&cursor[1 * NNA + dst], 1);
        srcs[1 * EED + pos] = __ldg(e1 + t);
    }
    {
        int dst = __ldg(e2 + EED + t);
        int pos = atomicAdd(&cursor[2 * NNA + dst], 1);
        srcs[2 * EED + pos] = __ldg(e2 + t);
    }
}

// ---------------- fused CSR aggregation + beta combine (merged A+B) ----------------
__device__ __forceinline__ void accum8(float* acc, uint4 v, float ex) {
    __half2* h2 = (__half2*)&v;
#pragma unroll
    for (int j = 0; j < 4; j++) {
        float2 f = __half22float2(h2[j]);
        acc[2 * j + 0] = fmaf(ex, f.x, acc[2 * j + 0]);
        acc[2 * j + 1] = fmaf(ex, f.y, acc[2 * j + 1]);
    }
}

__device__ __forceinline__ void csr_walk(const int* __restrict__ srcs,
                                         int start, int end,
                                         const float* __restrict__ al,
                                         int head, float arh,
                                         const __half* __restrict__ hs,
                                         int lane, float* acc, float& den) {
    for (int base = start; base < end; base += 32) {
        int n = min(32, end - base);
        int mysrc = (base + lane < end) ? __ldg(srcs + base + lane) : 0;
        int i = 0;
        for (; i + 4 <= n; i += 4) {
            int s0 = __shfl_sync(0xffffffffu, mysrc, i);
            int s1 = __shfl_sync(0xffffffffu, mysrc, i + 1);
            int s2 = __shfl_sync(0xffffffffu, mysrc, i + 2);
            int s3 = __shfl_sync(0xffffffffu, mysrc, i + 3);
            uint4 v0 = __ldg((const uint4*)(hs + (size_t)s0 * 256) + lane);
            uint4 v1 = __ldg((const uint4*)(hs + (size_t)s1 * 256) + lane);
            uint4 v2 = __ldg((const uint4*)(hs + (size_t)s2 * 256) + lane);
            uint4 v3 = __ldg((const uint4*)(hs + (size_t)s3 * 256) + lane);
            float ex0 = __expf(leaky02(__ldg(al + s0 * 8 + head) + arh));
            float ex1 = __expf(leaky02(__ldg(al + s1 * 8 + head) + arh));
            float ex2 = __expf(leaky02(__ldg(al + s2 * 8 + head) + arh));
            float ex3 = __expf(leaky02(__ldg(al + s3 * 8 + head) + arh));
            den += (ex0 + ex1) + (ex2 + ex3);
            accum8(acc, v0, ex0);
            accum8(acc, v1, ex1);
            accum8(acc, v2, ex2);
            accum8(acc, v3, ex3);
        }
        for (; i < n; i++) {
            int s0 = __shfl_sync(0xffffffffu, mysrc, i);
            uint4 v0 = __ldg((const uint4*)(hs + (size_t)s0 * 256) + lane);
            float ex0 = __expf(leaky02(__ldg(al + s0 * 8 + head) + arh));
            den += ex0;
            accum8(acc, v0, ex0);
        }
    }
}

__device__ __forceinline__ float quad_sum(float p) {
    p += __shfl_xor_sync(0xffffffffu, p, 1);
    p += __shfl_xor_sync(0xffffffffu, p, 2);
    return p;
}

__device__ __forceinline__ void load8f(const __half* hp, int lane, float* xs) {
    uint4 u = __ldg((const uint4*)hp + lane);
    __half2* h2 = (__half2*)&u;
#pragma unroll
    for (int j = 0; j < 4; j++) {
        float2 f = __half22float2(h2[j]);
        xs[2 * j + 0] = f.x;
        xs[2 * j + 1] = f.y;
    }
}

__global__ __launch_bounds__(256)
void aggbeta_all(const int* __restrict__ srcs_all, const int* __restrict__ rowptr,
                 const float* __restrict__ al1, const float* __restrict__ ar1,
                 const float* __restrict__ al2, const float* __restrict__ ar2,
                 const float* __restrict__ al0, const float* __restrict__ ar0,
                 const __half* __restrict__ hA16, const __half* __restrict__ hB16,
                 const float* __restrict__ blA, const float* __restrict__ blB,
                 const float* __restrict__ rel_r_A, const float* __restrict__ rel_r_B,
                 float* __restrict__ out) {
    int gw = blockIdx.x * 8 + (threadIdx.x >> 5);
    int lane = threadIdx.x & 31;
    if (gw >= NNA + NNB) return;
    int head = lane >> 2;

    if (gw < NNA) {
        int w = gw;
        float acc0[8], acc1[8];
#pragma unroll
        for (int j = 0; j < 8; j++) { acc0[j] = 0.f; acc1[j] = 0.f; }
        float den0 = 0.f, den1 = 0.f;
        {
            int s = __ldg(rowptr + 0 * RPSTR + w), e = __ldg(rowptr + 0 * RPSTR + w + 1);
            csr_walk(srcs_all + 0 * EED, s, e, al1, head,
                     __ldg(ar1 + w * 8 + head), hB16, lane, acc0, den0);
        }
        {
            int s = __ldg(rowptr + 1 * RPSTR + w), e = __ldg(rowptr + 1 * RPSTR + w + 1);
            csr_walk(srcs_all + 1 * EED, s, e, al2, head,
                     __ldg(ar2 + w * 8 + head), hA16, lane, acc1, den1);
        }
        float inv0 = den0 > 0.f ? 1.f / den0 : 0.f;
        float inv1 = den1 > 0.f ? 1.f / den1 : 0.f;
#pragma unroll
        for (int j = 0; j < 8; j++) { acc0[j] *= inv0; acc1[j] *= inv1; }

        float xs[8], rs[8];
        load8f(hA16 + (size_t)w * 256, lane, xs);
        {
            float4 r0 = __ldg((const float4*)rel_r_A + lane * 2);
            float4 r1 = __ldg((const float4*)rel_r_A + lane * 2 + 1);
            rs[0] = r0.x; rs[1] = r0.y; rs[2] = r0.z; rs[3] = r0.w;
            rs[4] = r1.x; rs[5] = r1.y; rs[6] = r1.z; rs[7] = r1.w;
        }
        float p0 = 0.f, p1 = 0.f, p2 = 0.f;
#pragma unroll
        for (int j = 0; j < 8; j++) {
            p0 = fmaf(acc0[j], rs[j], p0);
            p1 = fmaf(acc1[j], rs[j], p1);
            p2 = fmaf(xs[j],   rs[j], p2);
        }
        float b0 = quad_sum(p0), b1 = quad_sum(p1), b2 = quad_sum(p2);
        float bl = __ldg(blA + w * 8 + head);

        float s0 = leaky02(bl + b0);
        float s1 = leaky02(bl + b1);
        float s2 = leaky02(bl + b2);
        float mx = fmaxf(s0, fmaxf(s1, s2));
        float w0 = __expf(s0 - mx), w1 = __expf(s1 - mx), w2 = __expf(s2 - mx);
        float inv = 1.f / (w0 + w1 + w2);

        float o[8];
#pragma unroll
        for (int j = 0; j < 8; j++)
            o[j] = fmaxf((acc0[j] * w0 + acc1[j] * w1 + xs[j] * w2) * inv, 0.f);
        float4* op = (float4*)(out + (size_t)w * 256);
        op[lane * 2]     = make_float4(o[0], o[1], o[2], o[3]);
        op[lane * 2 + 1] = make_float4(o[4], o[5], o[6], o[7]);
    } else {
        int w = gw - NNA;
        float acc0[8];
#pragma unroll
        for (int j = 0; j < 8; j++) acc0[j] = 0.f;
        float den0 = 0.f;
        {
            int s = __ldg(rowptr + 2 * RPSTR + w), e = __ldg(rowptr + 2 * RPSTR + w + 1);
            csr_walk(srcs_all + 2 * EED, s, e, al0, head,
                     __ldg(ar0 + w * 8 + head), hA16, lane, acc0, den0);
        }
        float inv0 = den0 > 0.f ? 1.f / den0 : 0.f;
#pragma unroll
        for (int j = 0; j < 8; j++) acc0[j] *= inv0;

        float xs[8], rs[8];
        load8f(hB16 + (size_t)w * 256, lane, xs);
        {
            float4 r0 = __ldg((const float4*)rel_r_B + lane * 2);
            float4 r1 = __ldg((const float4*)rel_r_B + lane * 2 + 1);
            rs[0] = r0.x; rs[1] = r0.y; rs[2] = r0.z; rs[3] = r0.w;
            rs[4] = r1.x; rs[5] = r1.y; rs[6] = r1.z; rs[7] = r1.w;
        }
        float p0 = 0.f, p1 = 0.f;
#pragma unroll
        for (int j = 0; j < 8; j++) {
            p0 = fmaf(acc0[j], rs[j], p0);
            p1 = fmaf(xs[j],   rs[j], p1);
        }
        float b0 = quad_sum(p0), b1 = quad_sum(p1);
        float bl = __ldg(blB + w * 8 + head);

        float s0 = leaky02(bl + b0);
        float s1 = leaky02(bl + b1);
        float mx = fmaxf(s0, s1);
        float w0 = __expf(s0 - mx), w1 = __expf(s1 - mx);
        float inv = 1.f / (w0 + w1);

        float o[8];
#pragma unroll
        for (int j = 0; j < 8; j++)
            o[j] = fmaxf((acc0[j] * w0 + xs[j] * w1) * inv, 0.f);
        float4* op = (float4*)(out + (size_t)(NNA + w) * 256);
        op[lane * 2]     = make_float4(o[0], o[1], o[2], o[3]);
        op[lane * 2 + 1] = make_float4(o[4], o[5], o[6], o[7]);
    }
}

// ---------------- launch ----------------
extern "C" void kernel_launch(void* const* d_in, const int* in_sizes, int n_in,
                              void* d_out, int out_size) {
    const float* x_A     = (const float*)d_in[0];
    const float* x_B     = (const float*)d_in[1];
    const int*   e_ab    = (const int*)d_in[2];
    const int*   e_ba    = (const int*)d_in[3];
    const int*   e_aa    = (const int*)d_in[4];
    const float* W_A     = (const float*)d_in[5];
    const float* b_A     = (const float*)d_in[6];
    const float* W_B     = (const float*)d_in[7];
    const float* b_B     = (const float*)d_in[8];
    const float* attn_l  = (const float*)d_in[9];   // [3,8,32]
    const float* attn_r  = (const float*)d_in[10];
    const float* rel_l_A = (const float*)d_in[11];
    const float* rel_r_A = (const float*)d_in[12];
    const float* rel_l_B = (const float*)d_in[13];
    const float* rel_r_B = (const float*)d_in[14];
    float* out = (float*)d_out;

    void *p_hA16, *p_hB16;
    void *p_al0, *p_ar0, *p_al1, *p_ar1, *p_al2, *p_ar2, *p_blA, *p_blB;
    void *p_srcs, *p_cnt, *p_rowptr, *p_bsum;
    cudaGetSymbolAddress(&p_hA16, g_hA16);
    cudaGetSymbolAddress(&p_hB16, g_hB16);
    cudaGetSymbolAddress(&p_al0, g_al0);
    cudaGetSymbolAddress(&p_ar0, g_ar0);
    cudaGetSymbolAddress(&p_al1, g_al1);
    cudaGetSymbolAddress(&p_ar1, g_ar1);
    cudaGetSymbolAddress(&p_al2, g_al2);
    cudaGetSymbolAddress(&p_ar2, g_ar2);
    cudaGetSymbolAddress(&p_blA, g_blA);
    cudaGetSymbolAddress(&p_blB, g_blB);
    cudaGetSymbolAddress(&p_srcs, g_srcs);
    cudaGetSymbolAddress(&p_cnt, g_cnt);
    cudaGetSymbolAddress(&p_rowptr, g_rowptr);
    cudaGetSymbolAddress(&p_bsum, g_blocksum);

    int* cnt    = (int*)p_cnt;
    int* rowptr = (int*)p_rowptr;
    int* srcs   = (int*)p_srcs;
    int* bsum   = (int*)p_bsum;

    cudaMemsetAsync(cnt, 0, sizeof(int) * 3 * NNA, 0);

    // counting sort: count -> hierarchical scan -> scatter
    {
        int g = (EED + 255) / 256;
        count3_kernel<<<g, 256>>>(e_ba, e_aa, e_ab, cnt);
        scan_blocks<<<120, 256>>>(cnt, rowptr, bsum);
        scan_top<<<1, 96>>>(bsum, rowptr);
        scan_add<<<120, 256>>>(rowptr, bsum, cnt);
        scatter3_kernel<<<g, 256>>>(e_ba, e_aa, e_ab, cnt, srcs);
    }

    // merged projections (A and B) with fused per-node dots, fp16 h output
    {
        dim3 grid((NNA + 127) / 128, 4, 2);
        gemm_fused2<<<grid, 256>>>(x_A, x_B, W_A, W_B, b_A, b_B,
                                   (__half*)p_hA16, (__half*)p_hB16,
                                   attn_l, attn_r, rel_l_A, rel_l_B,
                                   (float*)p_al0, (float*)p_ar1,
                                   (float*)p_al2, (float*)p_ar2, (float*)p_blA,
                                   (float*)p_ar0, (float*)p_al1, (float*)p_blB);
    }

    // merged fused aggregation + beta + relu -> output
    aggbeta_all<<<(NNA + NNB + 7) / 8, 256>>>(srcs, rowptr,
                                              (float*)p_al1, (float*)p_ar1,
                                              (float*)p_al2, (float*)p_ar2,
                                              (float*)p_al0, (float*)p_ar0,
                                              (const __half*)p_hA16,
                                              (const __half*)p_hB16,
                                              (float*)p_blA, (float*)p_blB,
                                              rel_r_A, rel_r_B, out);

    (void)in_sizes; (void)n_in; (void)out_size;
}

// round 8
// speedup vs baseline: 3.2575x; 1.0362x over previous
#include <cuda_runtime.h>
#include <cuda_bf16.h>
#include <cuda_fp16.h>
#include <math.h>
#include <stdint.h>

// Problem constants (fixed shapes per reference)
#define NNA 40000
#define NNB 40000
#define EED 400000
#define DD  256
#define HH  8
#define RPSTR 40004   // rowptr per-relation stride

// ---------------- scratch (static device globals; no allocation) ----------------
__device__ __half g_hA16[NNA * DD];
__device__ __half g_hB16[NNB * DD];
__device__ __nv_bfloat16 g_Whi[2 * 65536];  // W split hi, [side][k][n]  (K-major, no transpose)
__device__ __nv_bfloat16 g_Wlo[2 * 65536];
__device__ float  g_al0[NNA * HH];
__device__ float  g_ar0[NNB * HH];
__device__ float  g_al1[NNB * HH];
__device__ float  g_ar1[NNA * HH];
__device__ float  g_al2[NNA * HH];
__device__ float  g_ar2[NNA * HH];
__device__ float  g_blA[NNA * HH];
__device__ float  g_blB[NNB * HH];
__device__ int    g_srcs[3 * EED];
__device__ int    g_cnt[3 * NNA];
__device__ int    g_rowptr[3 * RPSTR];
__device__ int    g_blocksum[128];

// ---------------- helpers ----------------
__device__ __forceinline__ float leaky02(float x) { return x > 0.f ? x : 0.2f * x; }

__device__ __forceinline__ uint32_t smem_u32(const void* p) {
    uint32_t a;
    asm("{ .reg .u64 t; cvta.to.shared.u64 t, %1; cvt.u32.u64 %0, t; }" : "=r"(a) : "l"(p));
    return a;
}
__device__ __forceinline__ void ldsm4(uint32_t* r, uint32_t a) {
    asm volatile("ldmatrix.sync.aligned.m8n8.x4.shared.b16 {%0,%1,%2,%3}, [%4];"
                 : "=r"(r[0]), "=r"(r[1]), "=r"(r[2]), "=r"(r[3]) : "r"(a));
}
__device__ __forceinline__ void ldsm4t(uint32_t* r, uint32_t a) {
    asm volatile("ldmatrix.sync.aligned.m8n8.x4.trans.shared.b16 {%0,%1,%2,%3}, [%4];"
                 : "=r"(r[0]), "=r"(r[1]), "=r"(r[2]), "=r"(r[3]) : "r"(a));
}
__device__ __forceinline__ void mma16816(float* d, const uint32_t* a, uint32_t b0, uint32_t b1) {
    asm volatile("mma.sync.aligned.m16n8k16.row.col.f32.bf16.bf16.f32 "
                 "{%0,%1,%2,%3}, {%4,%5,%6,%7}, {%8,%9}, {%0,%1,%2,%3};"
                 : "+f"(d[0]), "+f"(d[1]), "+f"(d[2]), "+f"(d[3])
                 : "r"(a[0]), "r"(a[1]), "r"(a[2]), "r"(a[3]), "r"(b0), "r"(b1));
}
__device__ __forceinline__ void split_one(float v, __nv_bfloat16& h, __nv_bfloat16& l) {
    h = __float2bfloat16(v);
    l = __float2bfloat16(v - __bfloat162float(h));
}
__device__ __forceinline__ void split_pair(float a, float b, uint32_t& hi, uint32_t& lo) {
    __nv_bfloat16 ah, al, bh, bl;
    split_one(a, ah, al); split_one(b, bh, bl);
    __nv_bfloat162 H; H.x = ah; H.y = bh;
    __nv_bfloat162 L; L.x = al; L.y = bl;
    hi = *reinterpret_cast<uint32_t*>(&H);
    lo = *reinterpret_cast<uint32_t*>(&L);
}

// ---------------- W bf16 split (runs once, tiny, K-major kept) ----------------
__global__ __launch_bounds__(256)
void wsplit_kernel(const float* __restrict__ WA, const float* __restrict__ WB,
                   __nv_bfloat16* __restrict__ Whi, __nv_bfloat16* __restrict__ Wlo) {
    const float* W = blockIdx.y ? WB : WA;
    __nv_bfloat16* hi = Whi + blockIdx.y * 65536;
    __nv_bfloat16* lo = Wlo + blockIdx.y * 65536;
    int i = (blockIdx.x * 256 + threadIdx.x) * 4;   // grid.x = 64
    float4 v = __ldg((const float4*)(W + i));
    uint32_t h01, l01, h23, l23;
    split_pair(v.x, v.y, h01, l01);
    split_pair(v.z, v.w, h23, l23);
    *(uint2*)(hi + i) = make_uint2(h01, h23);
    *(uint2*)(lo + i) = make_uint2(l01, l23);
}

// ---------------- merged GEMM (A and B sides via blockIdx.z) -----------------------
// h16 = fp16(x @ W + bias); fused per-node dots o[n,h] = sum_c h[n,h,c]*v[h,c]
#define ASTR 40
#define BSTR 72
__global__ __launch_bounds__(256)
void gemm_fused2(const float* __restrict__ xA, const float* __restrict__ xB,
                 const __nv_bfloat16* __restrict__ Whi, const __nv_bfloat16* __restrict__ Wlo,
                 const float* __restrict__ bA_, const float* __restrict__ bB_,
                 __half* __restrict__ hA16, __half* __restrict__ hB16,
                 const float* __restrict__ attn_l, const float* __restrict__ attn_r,
                 const float* __restrict__ rel_l_A, const float* __restrict__ rel_l_B,
                 float* __restrict__ al0, float* __restrict__ ar1,
                 float* __restrict__ al2, float* __restrict__ ar2,
                 float* __restrict__ blA,
                 float* __restrict__ ar0, float* __restrict__ al1,
                 float* __restrict__ blB) {
    __shared__ __nv_bfloat16 sAhi[128 * ASTR];
    __shared__ __nv_bfloat16 sAlo[128 * ASTR];
    __shared__ __nv_bfloat16 sBhi[32 * BSTR];
    __shared__ __nv_bfloat16 sBlo[32 * BSTR];
    __shared__ float sattn[5][64];
    __shared__ float sbias[64];
    __shared__ float spart[4][128];

    const int tid  = threadIdx.x;
    const int lane = tid & 31;
    const int wid  = tid >> 5;
    const int wm   = wid & 1;
    const int wn   = wid >> 1;
    const int row0 = blockIdx.x * 128;
    const int col0 = blockIdx.y * 64;
    const int M = NNA;

    const float* A; const float* bias; __half* C16;
    const __nv_bfloat16* Bh; const __nv_bfloat16* Bl;
    const float* vp[5]; float* op[5];
    if (blockIdx.z == 0) {
        A = xA; bias = bA_; C16 = hA16;
        Bh = Whi; Bl = Wlo;
        vp[0] = attn_l + 0;   op[0] = al0;
        vp[1] = attn_r + 256; op[1] = ar1;
        vp[2] = attn_l + 512; op[2] = al2;
        vp[3] = attn_r + 512; op[3] = ar2;
        vp[4] = rel_l_A;      op[4] = blA;
    } else {
        A = xB; bias = bB_; C16 = hB16;
        Bh = Whi + 65536; Bl = Wlo + 65536;
        vp[0] = attn_r + 0;   op[0] = ar0;
        vp[1] = attn_l + 256; op[1] = al1;
        vp[2] = 0;            op[2] = 0;
        vp[3] = 0;            op[3] = 0;
        vp[4] = rel_l_B;      op[4] = blB;
    }

    if (tid < 64) sbias[tid] = __ldg(bias + col0 + tid);
#pragma unroll
    for (int v = 0; v < 5; v++)
        if (vp[v] && tid < 64) sattn[v][tid] = __ldg(vp[v] + col0 + tid);

    float acc[4][2][4];
#pragma unroll
    for (int i = 0; i < 4; i++)
#pragma unroll
        for (int j = 0; j < 2; j++)
#pragma unroll
            for (int k = 0; k < 4; k++) acc[i][j][k] = 0.f;

    float4 av[4];
    uint2 bvh[2], bvl[2];
#pragma unroll
    for (int p = 0; p < 4; p++) {
        int f = tid + 256 * p, r = f >> 3, c = (f & 7) * 4;
        int gr = row0 + r;
        av[p] = (gr < M) ? __ldg((const float4*)(A + (size_t)gr * 256 + c))
                         : make_float4(0.f, 0.f, 0.f, 0.f);
    }
#pragma unroll
    for (int p = 0; p < 2; p++) {
        int f = tid + 256 * p, r = f >> 4, c = (f & 15) * 4;
        bvh[p] = __ldg((const uint2*)(Bh + (size_t)r * 256 + col0 + c));
        bvl[p] = __ldg((const uint2*)(Bl + (size_t)r * 256 + col0 + c));
    }

    for (int kb = 0; kb < 8; kb++) {
#pragma unroll
        for (int p = 0; p < 4; p++) {
            int f = tid + 256 * p, r = f >> 3, c = (f & 7) * 4;
            uint32_t h01, l01, h23, l23;
            split_pair(av[p].x, av[p].y, h01, l01);
            split_pair(av[p].z, av[p].w, h23, l23);
            *(uint2*)&sAhi[r * ASTR + c] = make_uint2(h01, h23);
            *(uint2*)&sAlo[r * ASTR + c] = make_uint2(l01, l23);
        }
#pragma unroll
        for (int p = 0; p < 2; p++) {
            int f = tid + 256 * p, r = f >> 4, c = (f & 15) * 4;
            *(uint2*)&sBhi[r * BSTR + c] = bvh[p];
            *(uint2*)&sBlo[r * BSTR + c] = bvl[p];
        }
        __syncthreads();

        if (kb < 7) {
            int k0 = (kb + 1) * 32;
#pragma unroll
            for (int p = 0; p < 4; p++) {
                int f = tid + 256 * p, r = f >> 3, c = (f & 7) * 4;
                int gr = row0 + r;
                av[p] = (gr < M) ? __ldg((const float4*)(A + (size_t)gr * 256 + k0 + c))
                                 : make_float4(0.f, 0.f, 0.f, 0.f);
            }
#pragma unroll
            for (int p = 0; p < 2; p++) {
                int f = tid + 256 * p, r = f >> 4, c = (f & 15) * 4;
                bvh[p] = __ldg((const uint2*)(Bh + (size_t)(k0 + r) * 256 + col0 + c));
                bvl[p] = __ldg((const uint2*)(Bl + (size_t)(k0 + r) * 256 + col0 + c));
            }
        }

#pragma unroll
        for (int kk = 0; kk < 32; kk += 16) {
            uint32_t ahi[4][4], alo[4][4], bh[4], bl[4];
            int arow = wm * 64 + (lane & 15);
            int acol = kk + ((lane >> 4) << 3);
#pragma unroll
            for (int mt = 0; mt < 4; mt++)
                ldsm4(ahi[mt], smem_u32(&sAhi[(arow + mt * 16) * ASTR + acol]));
            {
                int brow = kk + (lane & 7) + ((lane >> 3) & 1) * 8;
                int bcol = wn * 16 + ((lane >> 4) << 3);
                ldsm4t(bh, smem_u32(&sBhi[brow * BSTR + bcol]));
                ldsm4t(bl, smem_u32(&sBlo[brow * BSTR + bcol]));
            }
#pragma unroll
            for (int mt = 0; mt < 4; mt++)
                ldsm4(alo[mt], smem_u32(&sAlo[(arow + mt * 16) * ASTR + acol]));

#pragma unroll
            for (int mt = 0; mt < 4; mt++)
#pragma unroll
                for (int nt = 0; nt < 2; nt++) {
                    mma16816(acc[mt][nt], ahi[mt], bh[nt * 2], bh[nt * 2 + 1]);
                    mma16816(acc[mt][nt], ahi[mt], bl[nt * 2], bl[nt * 2 + 1]);
                    mma16816(acc[mt][nt], alo[mt], bh[nt * 2], bh[nt * 2 + 1]);
                }
        }
        __syncthreads();
    }

    // ---- epilogue: bias, store fp16 ----
#pragma unroll
    for (int mt = 0; mt < 4; mt++)
#pragma unroll
        for (int nt = 0; nt < 2; nt++) {
            int cl = wn * 16 + nt * 8 + (lane & 3) * 2;
#pragma unroll
            for (int half = 0; half < 2; half++) {
                acc[mt][nt][half * 2 + 0] += sbias[cl + 0];
                acc[mt][nt][half * 2 + 1] += sbias[cl + 1];
            }
        }
#pragma unroll
    for (int mt = 0; mt < 4; mt++)
#pragma unroll
        for (int half = 0; half < 2; half++) {
            int gr = row0 + wm * 64 + mt * 16 + (lane >> 2) + half * 8;
            if (gr < M) {
#pragma unroll
                for (int nt = 0; nt < 2; nt++) {
                    int gc = col0 + wn * 16 + nt * 8 + (lane & 3) * 2;
                    *(__half2*)(C16 + (size_t)gr * 256 + gc) =
                        __floats2half2_rn(acc[mt][nt][half * 2 + 0],
                                          acc[mt][nt][half * 2 + 1]);
                }
            }
        }

    // ---- fused per-node dots ----
#pragma unroll
    for (int v = 0; v < 5; v++) {
        if (!vp[v]) continue;
        __syncthreads();
#pragma unroll
        for (int mt = 0; mt < 4; mt++)
#pragma unroll
            for (int half = 0; half < 2; half++) {
                float p = 0.f;
#pragma unroll
                for (int nt = 0; nt < 2; nt++) {
                    int cl = wn * 16 + nt * 8 + (lane & 3) * 2;
                    p = fmaf(acc[mt][nt][half * 2 + 0], sattn[v][cl + 0], p);
                    p = fmaf(acc[mt][nt][half * 2 + 1], sattn[v][cl + 1], p);
                }
                p += __shfl_xor_sync(0xffffffffu, p, 1);
                p += __shfl_xor_sync(0xffffffffu, p, 2);
                if ((lane & 3) == 0)
                    spart[wn][wm * 64 + mt * 16 + (lane >> 2) + half * 8] = p;
            }
        __syncthreads();
        {
            int row = tid >> 1, j = tid & 1;
            int gr = row0 + row;
            if (gr < M)
                op[v][(size_t)gr * 8 + blockIdx.y * 2 + j] =
                    spart[2 * j][row] + spart[2 * j + 1][row];
        }
    }
}

// ---------------- counting sort by dst (3 relations) ----------------
__global__ __launch_bounds__(256)
void count3_kernel(const int* __restrict__ e0, const int* __restrict__ e1,
                   const int* __restrict__ e2, int* __restrict__ cnt) {
    int t = blockIdx.x * 256 + threadIdx.x;
    if (t >= EED) return;
    atomicAdd(&cnt[0 * NNA + __ldg(e0 + EED + t)], 1);
    atomicAdd(&cnt[1 * NNA + __ldg(e1 + EED + t)], 1);
    atomicAdd(&cnt[2 * NNA + __ldg(e2 + EED + t)], 1);
}

__global__ __launch_bounds__(256)
void scan_blocks(const int* __restrict__ cnt, int* __restrict__ rowptr,
                 int* __restrict__ blocksum) {
    int bx = blockIdx.x;           // 0..119
    int r = bx / 40, ch = bx % 40;
    const int4* c4 = (const int4*)(cnt + r * NNA + ch * 1000);
    int4* rp4 = (int4*)(rowptr + r * RPSTR + ch * 1000);
    int t = threadIdx.x, lane = t & 31, wid = t >> 5;

    int4 v = make_int4(0, 0, 0, 0);
    if (t < 250) v = c4[t];
    int ts = v.x + v.y + v.z + v.w;

    int inc = ts;
#pragma unroll
    for (int off = 1; off < 32; off <<= 1) {
        int u = __shfl_up_sync(0xffffffffu, inc, off);
        if (lane >= off) inc += u;
    }
    __shared__ int wsum[8];
    if (lane == 31) wsum[wid] = inc;
    __syncthreads();
    if (wid == 0) {
        int x = (lane < 8) ? wsum[lane] : 0;
#pragma unroll
        for (int off = 1; off < 8; off <<= 1) {
            int u = __shfl_up_sync(0xffffffffu, x, off);
            if (lane >= off) x += u;
        }
        if (lane < 8) wsum[lane] = x;
    }
    __syncthreads();
    int excl = ((wid == 0) ? 0 : wsum[wid - 1]) + inc - ts;
    if (t < 250) {
        int4 o;
        o.x = excl;
        o.y = excl + v.x;
        o.z = o.y + v.y;
        o.w = o.z + v.z;
        rp4[t] = o;
    }
    if (t == 0) blocksum[bx] = wsum[7];
}

__global__ __launch_bounds__(96)
void scan_top(int* __restrict__ blocksum, int* __restrict__ rowptr) {
    int r = threadIdx.x >> 5;
    int lane = threadIdx.x & 31;
    int* bs = blocksum + r * 40;
    int a = __ldg(bs + lane);
    int b = (lane < 8) ? __ldg(bs + 32 + lane) : 0;
    int ia = a, ib = b;
#pragma unroll
    for (int off = 1; off < 32; off <<= 1) {
        int u = __shfl_up_sync(0xffffffffu, ia, off);
        if (lane >= off) ia += u;
    }
#pragma unroll
    for (int off = 1; off < 8; off <<= 1) {
        int u = __shfl_up_sync(0xffffffffu, ib, off);
        if (lane >= off) ib += u;
    }
    int tot32 = __shfl_sync(0xffffffffu, ia, 31);
    int totb  = __shfl_sync(0xffffffffu, ib, 7);
    bs[lane] = ia - a;
    if (lane < 8) bs[32 + lane] = tot32 + ib - b;
    if (lane == 0) rowptr[r * RPSTR + NNA] = tot32 + totb;
}

__global__ __launch_bounds__(256)
void scan_add(int* __restrict__ rowptr, const int* __restrict__ blocksum,
              int* __restrict__ cnt) {
    int bx = blockIdx.x;
    int r = bx / 40, ch = bx % 40;
    int t = threadIdx.x;
    if (t >= 250) return;
    int off = __ldg(blocksum + bx);
    int4* rp4 = (int4*)(rowptr + r * RPSTR + ch * 1000);
    int4* cu4 = (int4*)(cnt + r * NNA + ch * 1000);
    int4 v = rp4[t];
    v.x += off; v.y += off; v.z += off; v.w += off;
    rp4[t] = v;
    cu4[t] = v;
}

__global__ __launch_bounds__(256)
void scatter3_kernel(const int* __restrict__ e0, const int* __restrict__ e1,
                     const int* __restrict__ e2,
                     int* __restrict__ cursor, int* __restrict__ srcs) {
    int t = blockIdx.x * 256 + threadIdx.x;
    if (t >= EED) return;
    {
        int dst = __ldg(e0 + EED + t);
        int pos = atomicAdd(&cursor[0 * NNA + dst], 1);
        srcs[0 * EED + pos] = __ldg(e0 + t);
    }
    {
        int dst = __ldg(e1 + EED + t);
        int pos = atomicAdd(&cursor[1 * NNA + dst], 1);
        srcs[1 * EED + pos] = __ldg(e1 + t);
    }
    {
        int dst = __ldg(e2 + EED + t);
        int pos = atomicAdd(&cursor[2 * NNA + dst], 1);
        srcs[2 * EED + pos] = __ldg(e2 + t);
    }
}

// ---------------- fused CSR aggregation + beta combine (merged A+B) ----------------
__device__ __forceinline__ void accum8(float* acc, uint4 v, float ex) {
    __half2* h2 = (__half2*)&v;
#pragma unroll
    for (int j = 0; j < 4; j++) {
        float2 f = __half22float2(h2[j]);
        acc[2 * j + 0] = fmaf(ex, f.x, acc[2 * j + 0]);
        acc[2 * j + 1] = fmaf(ex, f.y, acc[2 * j + 1]);
    }
}

__device__ __forceinline__ void csr_walk(const int* __restrict__ srcs,
                                         int start, int end,
                                         const float* __restrict__ al,
                                         int head, float arh,
                                         const __half* __restrict__ hs,
                                         int lane, float* acc, float& den) {
    for (int base = start; base < end; base += 32) {
        int n = min(32, end - base);
        int mysrc = (base + lane < end) ? __ldg(srcs + base + lane) : 0;
        int i = 0;
        for (; i + 4 <= n; i += 4) {
            int s0 = __shfl_sync(0xffffffffu, mysrc, i);
            int s1 = __shfl_sync(0xffffffffu, mysrc, i + 1);
            int s2 = __shfl_sync(0xffffffffu, mysrc, i + 2);
            int s3 = __shfl_sync(0xffffffffu, mysrc, i + 3);
            uint4 v0 = __ldg((const uint4*)(hs + (size_t)s0 * 256) + lane);
            uint4 v1 = __ldg((const uint4*)(hs + (size_t)s1 * 256) + lane);
            uint4 v2 = __ldg((const uint4*)(hs + (size_t)s2 * 256) + lane);
            uint4 v3 = __ldg((const uint4*)(hs + (size_t)s3 * 256) + lane);
            float ex0 = __expf(leaky02(__ldg(al + s0 * 8 + head) + arh));
            float ex1 = __expf(leaky02(__ldg(al + s1 * 8 + head) + arh));
            float ex2 = __expf(leaky02(__ldg(al + s2 * 8 + head) + arh));
            float ex3 = __expf(leaky02(__ldg(al + s3 * 8 + head) + arh));
            den += (ex0 + ex1) + (ex2 + ex3);
            accum8(acc, v0, ex0);
            accum8(acc, v1, ex1);
            accum8(acc, v2, ex2);
            accum8(acc, v3, ex3);
        }
        for (; i < n; i++) {
            int s0 = __shfl_sync(0xffffffffu, mysrc, i);
            uint4 v0 = __ldg((const uint4*)(hs + (size_t)s0 * 256) + lane);
            float ex0 = __expf(leaky02(__ldg(al + s0 * 8 + head) + arh));
            den += ex0;
            accum8(acc, v0, ex0);
        }
    }
}

__device__ __forceinline__ float quad_sum(float p) {
    p += __shfl_xor_sync(0xffffffffu, p, 1);
    p += __shfl_xor_sync(0xffffffffu, p, 2);
    return p;
}

__device__ __forceinline__ void load8f(const __half* hp, int lane, float* xs) {
    uint4 u = __ldg((const uint4*)hp + lane);
    __half2* h2 = (__half2*)&u;
#pragma unroll
    for (int j = 0; j < 4; j++) {
        float2 f = __half22float2(h2[j]);
        xs[2 * j + 0] = f.x;
        xs[2 * j + 1] = f.y;
    }
}

__global__ __launch_bounds__(256)
void aggbeta_all(const int* __restrict__ srcs_all, const int* __restrict__ rowptr,
                 const float* __restrict__ al1, const float* __restrict__ ar1,
                 const float* __restrict__ al2, const float* __restrict__ ar2,
                 const float* __restrict__ al0, const float* __restrict__ ar0,
                 const __half* __restrict__ hA16, const __half* __restrict__ hB16,
                 const float* __restrict__ blA, const float* __restrict__ blB,
                 const float* __restrict__ rel_r_A, const float* __restrict__ rel_r_B,
                 float* __restrict__ out) {
    int gw = blockIdx.x * 8 + (threadIdx.x >> 5);
    int lane = threadIdx.x & 31;
    if (gw >= NNA + NNB) return;
    int head = lane >> 2;

    if (gw < NNA) {
        int w = gw;
        float acc0[8], acc1[8];
#pragma unroll
        for (int j = 0; j < 8; j++) { acc0[j] = 0.f; acc1[j] = 0.f; }
        float den0 = 0.f, den1 = 0.f;
        {
            int s = __ldg(rowptr + 0 * RPSTR + w), e = __ldg(rowptr + 0 * RPSTR + w + 1);
            csr_walk(srcs_all + 0 * EED, s, e, al1, head,
                     __ldg(ar1 + w * 8 + head), hB16, lane, acc0, den0);
        }
        {
            int s = __ldg(rowptr + 1 * RPSTR + w), e = __ldg(rowptr + 1 * RPSTR + w + 1);
            csr_walk(srcs_all + 1 * EED, s, e, al2, head,
                     __ldg(ar2 + w * 8 + head), hA16, lane, acc1, den1);
        }
        float inv0 = den0 > 0.f ? 1.f / den0 : 0.f;
        float inv1 = den1 > 0.f ? 1.f / den1 : 0.f;
#pragma unroll
        for (int j = 0; j < 8; j++) { acc0[j] *= inv0; acc1[j] *= inv1; }

        float xs[8], rs[8];
        load8f(hA16 + (size_t)w * 256, lane, xs);
        {
            float4 r0 = __ldg((const float4*)rel_r_A + lane * 2);
            float4 r1 = __ldg((const float4*)rel_r_A + lane * 2 + 1);
            rs[0] = r0.x; rs[1] = r0.y; rs[2] = r0.z; rs[3] = r0.w;
            rs[4] = r1.x; rs[5] = r1.y; rs[6] = r1.z; rs[7] = r1.w;
        }
        float p0 = 0.f, p1 = 0.f, p2 = 0.f;
#pragma unroll
        for (int j = 0; j < 8; j++) {
            p0 = fmaf(acc0[j], rs[j], p0);
            p1 = fmaf(acc1[j], rs[j], p1);
            p2 = fmaf(xs[j],   rs[j], p2);
        }
        float b0 = quad_sum(p0), b1 = quad_sum(p1), b2 = quad_sum(p2);
        float bl = __ldg(blA + w * 8 + head);

        float s0 = leaky02(bl + b0);
        float s1 = leaky02(bl + b1);
        float s2 = leaky02(bl + b2);
        float mx = fmaxf(s0, fmaxf(s1, s2));
        float w0 = __expf(s0 - mx), w1 = __expf(s1 - mx), w2 = __expf(s2 - mx);
        float inv = 1.f / (w0 + w1 + w2);

        float o[8];
#pragma unroll
        for (int j = 0; j < 8; j++)
            o[j] = fmaxf((acc0[j] * w0 + acc1[j] * w1 + xs[j] * w2) * inv, 0.f);
        float4* op = (float4*)(out + (size_t)w * 256);
        op[lane * 2]     = make_float4(o[0], o[1], o[2], o[3]);
        op[lane * 2 + 1] = make_float4(o[4], o[5], o[6], o[7]);
    } else {
        int w = gw - NNA;
        float acc0[8];
#pragma unroll
        for (int j = 0; j < 8; j++) acc0[j] = 0.f;
        float den0 = 0.f;
        {
            int s = __ldg(rowptr + 2 * RPSTR + w), e = __ldg(rowptr + 2 * RPSTR + w + 1);
            csr_walk(srcs_all + 2 * EED, s, e, al0, head,
                     __ldg(ar0 + w * 8 + head), hA16, lane, acc0, den0);
        }
        float inv0 = den0 > 0.f ? 1.f / den0 : 0.f;
#pragma unroll
        for (int j = 0; j < 8; j++) acc0[j] *= inv0;

        float xs[8], rs[8];
        load8f(hB16 + (size_t)w * 256, lane, xs);
        {
            float4 r0 = __ldg((const float4*)rel_r_B + lane * 2);
            float4 r1 = __ldg((const float4*)rel_r_B + lane * 2 + 1);
            rs[0] = r0.x; rs[1] = r0.y; rs[2] = r0.z; rs[3] = r0.w;
            rs[4] = r1.x; rs[5] = r1.y; rs[6] = r1.z; rs[7] = r1.w;
        }
        float p0 = 0.f, p1 = 0.f;
#pragma unroll
        for (int j = 0; j < 8; j++) {
            p0 = fmaf(acc0[j], rs[j], p0);
            p1 = fmaf(xs[j],   rs[j], p1);
        }
        float b0 = quad_sum(p0), b1 = quad_sum(p1);
        float bl = __ldg(blB + w * 8 + head);

        float s0 = leaky02(bl + b0);
        float s1 = leaky02(bl + b1);
        float mx = fmaxf(s0, s1);
        float w0 = __expf(s0 - mx), w1 = __expf(s1 - mx);
        float inv = 1.f / (w0 + w1);

        float o[8];
#pragma unroll
        for (int j = 0; j < 8; j++)
            o[j] = fmaxf((acc0[j] * w0 + xs[j] * w1) * inv, 0.f);
        float4* op = (float4*)(out + (size_t)(NNA + w) * 256);
        op[lane * 2]     = make_float4(o[0], o[1], o[2], o[3]);
        op[lane * 2 + 1] = make_float4(o[4], o[5], o[6], o[7]);
    }
}

// ---------------- launch ----------------
extern "C" void kernel_launch(void* const* d_in, const int* in_sizes, int n_in,
                              void* d_out, int out_size) {
    const float* x_A     = (const float*)d_in[0];
    const float* x_B     = (const float*)d_in[1];
    const int*   e_ab    = (const int*)d_in[2];
    const int*   e_ba    = (const int*)d_in[3];
    const int*   e_aa    = (const int*)d_in[4];
    const float* W_A     = (const float*)d_in[5];
    const float* b_A     = (const float*)d_in[6];
    const float* W_B     = (const float*)d_in[7];
    const float* b_B     = (const float*)d_in[8];
    const float* attn_l  = (const float*)d_in[9];   // [3,8,32]
    const float* attn_r  = (const float*)d_in[10];
    const float* rel_l_A = (const float*)d_in[11];
    const float* rel_r_A = (const float*)d_in[12];
    const float* rel_l_B = (const float*)d_in[13];
    const float* rel_r_B = (const float*)d_in[14];
    float* out = (float*)d_out;

    void *p_hA16, *p_hB16, *p_Whi, *p_Wlo;
    void *p_al0, *p_ar0, *p_al1, *p_ar1, *p_al2, *p_ar2, *p_blA, *p_blB;
    void *p_srcs, *p_cnt, *p_rowptr, *p_bsum;
    cudaGetSymbolAddress(&p_hA16, g_hA16);
    cudaGetSymbolAddress(&p_hB16, g_hB16);
    cudaGetSymbolAddress(&p_Whi, g_Whi);
    cudaGetSymbolAddress(&p_Wlo, g_Wlo);
    cudaGetSymbolAddress(&p_al0, g_al0);
    cudaGetSymbolAddress(&p_ar0, g_ar0);
    cudaGetSymbolAddress(&p_al1, g_al1);
    cudaGetSymbolAddress(&p_ar1, g_ar1);
    cudaGetSymbolAddress(&p_al2, g_al2);
    cudaGetSymbolAddress(&p_ar2, g_ar2);
    cudaGetSymbolAddress(&p_blA, g_blA);
    cudaGetSymbolAddress(&p_blB, g_blB);
    cudaGetSymbolAddress(&p_srcs, g_srcs);
    cudaGetSymbolAddress(&p_cnt, g_cnt);
    cudaGetSymbolAddress(&p_rowptr, g_rowptr);
    cudaGetSymbolAddress(&p_bsum, g_blocksum);

    int* cnt    = (int*)p_cnt;
    int* rowptr = (int*)p_rowptr;
    int* srcs   = (int*)p_srcs;
    int* bsum   = (int*)p_bsum;

    // one-time infra (no device memory allocation)
    static cudaStream_t s1 = nullptr;
    static cudaEvent_t evFork = nullptr, evJoin = nullptr;
    if (!s1) {
        cudaStreamCreateWithFlags(&s1, cudaStreamNonBlocking);
        cudaEventCreateWithFlags(&evFork, cudaEventDisableTiming);
        cudaEventCreateWithFlags(&evJoin, cudaEventDisableTiming);
    }

    // fork: sort chain on s1 runs concurrently with wsplit+GEMM on stream 0
    cudaEventRecord(evFork, 0);
    cudaStreamWaitEvent(s1, evFork, 0);
    {
        cudaMemsetAsync(cnt, 0, sizeof(int) * 3 * NNA, s1);
        int g = (EED + 255) / 256;
        count3_kernel<<<g, 256, 0, s1>>>(e_ba, e_aa, e_ab, cnt);
        scan_blocks<<<120, 256, 0, s1>>>(cnt, rowptr, bsum);
        scan_top<<<1, 96, 0, s1>>>(bsum, rowptr);
        scan_add<<<120, 256, 0, s1>>>(rowptr, bsum, cnt);
        scatter3_kernel<<<g, 256, 0, s1>>>(e_ba, e_aa, e_ab, cnt, srcs);
        cudaEventRecord(evJoin, s1);
    }

    // stream 0: W split then merged projections
    {
        dim3 gw(64, 2);
        wsplit_kernel<<<gw, 256>>>(W_A, W_B, (__nv_bfloat16*)p_Whi, (__nv_bfloat16*)p_Wlo);
        dim3 grid((NNA + 127) / 128, 4, 2);
        gemm_fused2<<<grid, 256>>>(x_A, x_B,
                                   (const __nv_bfloat16*)p_Whi, (const __nv_bfloat16*)p_Wlo,
                                   b_A, b_B,
                                   (__half*)p_hA16, (__half*)p_hB16,
                                   attn_l, attn_r, rel_l_A, rel_l_B,
                                   (float*)p_al0, (float*)p_ar1,
                                   (float*)p_al2, (float*)p_ar2, (float*)p_blA,
                                   (float*)p_ar0, (float*)p_al1, (float*)p_blB);
    }

    // join: aggbeta needs both the GEMM outputs and the CSR
    cudaStreamWaitEvent(0, evJoin, 0);
    aggbeta_all<<<(NNA + NNB + 7) / 8, 256>>>(srcs, rowptr,
                                              (float*)p_al1, (float*)p_ar1,
                                              (float*)p_al2, (float*)p_ar2,
                                              (float*)p_al0, (float*)p_ar0,
                                              (const __half*)p_hA16,
                                              (const __half*)p_hB16,
                                              (float*)p_blA, (float*)p_blB,
                                              rel_r_A, rel_r_B, out);

    (void)in_sizes; (void)n_in; (void)out_size;
}